// round 4
// baseline (speedup 1.0000x reference)
#include <cuda_runtime.h>
#include <cuda_bf16.h>
#include <cstdint>

#define N_NODES 50000
#define N_EDGES 600000
#define N_GRAPHS 2000
#define IN_FEATS 64
#define HIDDEN 128
#define SCAN_BS 1024
#define SCAN_NB ((N_NODES + SCAN_BS - 1) / SCAN_BS)   // 49

typedef unsigned long long u64;

// ---------------- scratch (device globals; no allocation allowed) ----------
__device__ int   g_deg_out[N_NODES];
__device__ int   g_deg_in[N_NODES];
__device__ float g_cout[N_NODES];
__device__ float g_cin[N_NODES];
__device__ int   g_rowstart[N_NODES + 1];
__device__ int   g_fill[N_NODES];
__device__ int   g_scanagg[SCAN_NB];
__device__ int   g_scanflag[SCAN_NB];
__device__ int   g_csr_src[N_EDGES];
__device__ float g_x[(size_t)N_NODES * HIDDEN];
__device__ float g_y[(size_t)N_NODES * HIDDEN];
__device__ float g_gsum[(size_t)N_GRAPHS * HIDDEN];
__device__ int   g_gcnt[N_GRAPHS];

// ---------------- helpers ---------------------------------------------------
__device__ __forceinline__ void red_add_v4(float* p, float4 v) {
    asm volatile("red.global.add.v4.f32 [%0], {%1, %2, %3, %4};"
                 :: "l"(p), "f"(v.x), "f"(v.y), "f"(v.z), "f"(v.w)
                 : "memory");
}
__device__ __forceinline__ u64 pack2(float lo, float hi) {
    u64 r; asm("mov.b64 %0, {%1, %2};" : "=l"(r) : "f"(lo), "f"(hi)); return r;
}
__device__ __forceinline__ u64 fma2(u64 a, u64 b, u64 c) {
    u64 d; asm("fma.rn.f32x2 %0, %1, %2, %3;" : "=l"(d) : "l"(a), "l"(b), "l"(c)); return d;
}
__device__ __forceinline__ float2 unpack2(u64 v) {
    float2 f; asm("mov.b64 {%0, %1}, %2;" : "=f"(f.x), "=f"(f.y) : "l"(v)); return f;
}

// ---------------- zero + degree -----------------------------------------------
__global__ void zero_misc_kernel() {
    int i = blockIdx.x * blockDim.x + threadIdx.x;
    if (i < N_NODES) { g_deg_out[i] = 0; g_deg_in[i] = 0; }
    if (i < N_GRAPHS) g_gcnt[i] = 0;
    if (i < SCAN_NB) g_scanflag[i] = 0;
}

__global__ void degree_kernel(const int* __restrict__ src, const int* __restrict__ dst) {
    int e = blockIdx.x * blockDim.x + threadIdx.x;
    if (e < N_EDGES) {
        atomicAdd(&g_deg_out[src[e]], 1);
        atomicAdd(&g_deg_in[dst[e]], 1);
    }
}

// ---------------- single-kernel scan (decoupled lookback) + finalize ---------
// 49 blocks x 1024 threads, all co-resident -> spin-wait is deadlock-free.
__global__ __launch_bounds__(SCAN_BS)
void scan_kernel(const int* __restrict__ gid) {
    int b = blockIdx.x;
    int i = b * SCAN_BS + threadIdx.x;
    int lane = threadIdx.x & 31, wid = threadIdx.x >> 5;
    int v = (i < N_NODES) ? g_deg_in[i] : 0;
    int x = v;
#pragma unroll
    for (int o = 1; o < 32; o <<= 1) {
        int y = __shfl_up_sync(0xFFFFFFFFu, x, o);
        if (lane >= o) x += y;
    }
    __shared__ int wsum[32];
    __shared__ int s_prefix;
    if (lane == 31) wsum[wid] = x;
    __syncthreads();
    if (wid == 0) {
        int w = wsum[lane];
#pragma unroll
        for (int o = 1; o < 32; o <<= 1) {
            int y = __shfl_up_sync(0xFFFFFFFFu, w, o);
            if (lane >= o) w += y;
        }
        wsum[lane] = w;
    }
    __syncthreads();
    int excl = x - v + (wid > 0 ? wsum[wid - 1] : 0);

    // publish block aggregate, then look back over predecessors
    if (threadIdx.x == 0) {
        g_scanagg[b] = wsum[31];
        __threadfence();
        atomicExch(&g_scanflag[b], 1);
    }
    if (wid == 0) {
        int pre = 0;
        for (int base = 0; base < b; base += 32) {
            int idx = base + lane;
            int val = 0;
            if (idx < b) {
                while (atomicAdd(&g_scanflag[idx], 0) == 0) {}
                val = g_scanagg[idx];
            }
#pragma unroll
            for (int o = 16; o > 0; o >>= 1)
                val += __shfl_xor_sync(0xFFFFFFFFu, val, o);
            pre += val;
        }
        if (lane == 0) s_prefix = pre;
    }
    __syncthreads();
    int prefix = s_prefix;

    if (i < N_NODES) {
        int r = excl + prefix;
        g_rowstart[i] = r;
        g_fill[i] = r;
        g_cout[i] = rsqrtf(fmaxf((float)g_deg_out[i], 1.0f));
        g_cin[i]  = rsqrtf(fmaxf((float)g_deg_in[i], 1.0f));
        atomicAdd(&g_gcnt[gid[i]], 1);
    }
    if (i == 0) g_rowstart[N_NODES] = N_EDGES;

    // zero the pool accumulator (consumed by gconv3, launched later)
    for (int k = b * SCAN_BS + threadIdx.x; k < N_GRAPHS * HIDDEN; k += SCAN_NB * SCAN_BS)
        g_gsum[k] = 0.0f;
}

__global__ void fill_kernel(const int* __restrict__ src, const int* __restrict__ dst) {
    int e = blockIdx.x * blockDim.x + threadIdx.x;
    if (e < N_EDGES) {
        int pos = atomicAdd(&g_fill[dst[e]], 1);
        g_csr_src[pos] = src[e];
    }
}

// ---------------- fused gconv: pull-aggregate into smem, then f32x2 GEMM -----
// out = act( [c_in * sum_{s in N(d)} x[s] (*c_out[s])] @ W + b ) (*c_out[d])
// BM=64 rows/block, BN=128, BK=16. 256 threads.
template <int FIN, bool SCALE_COUT, bool RELU, bool SCALE_OUT, bool POOL>
__global__ __launch_bounds__(256)
void gconv_kernel(const float* __restrict__ x,
                  const float* __restrict__ W,
                  const float* __restrict__ bias,
                  float* __restrict__ C,
                  const int* __restrict__ gid) {
    __shared__ float At[FIN][66];    // aggregated A tile, k-major: [k][row]
    __shared__ float Ws[16][128];

    int tid = threadIdx.x;
    int rowBase = blockIdx.x * 64;

    // ---- phase 1: pull aggregation straight into smem (k-major) ----
    constexpr int LPN = FIN / 4;     // lanes (float4 slots) per node
    for (int t = tid; t < 64 * LPN; t += 256) {
        int row = t / LPN;
        int lane = t % LPN;
        int gr = rowBase + row;
        float4 acc = make_float4(0.f, 0.f, 0.f, 0.f);
        if (gr < N_NODES) {
            int j = __ldg(&g_rowstart[gr]);
            int end = __ldg(&g_rowstart[gr + 1]);
            for (; j + 1 < end; j += 2) {
                int s0 = __ldg(&g_csr_src[j]);
                int s1 = __ldg(&g_csr_src[j + 1]);
                float4 v0 = __ldg(reinterpret_cast<const float4*>(x + (size_t)s0 * FIN + lane * 4));
                float4 v1 = __ldg(reinterpret_cast<const float4*>(x + (size_t)s1 * FIN + lane * 4));
                float c0 = SCALE_COUT ? __ldg(&g_cout[s0]) : 1.0f;
                float c1 = SCALE_COUT ? __ldg(&g_cout[s1]) : 1.0f;
                acc.x = fmaf(v0.x, c0, acc.x); acc.y = fmaf(v0.y, c0, acc.y);
                acc.z = fmaf(v0.z, c0, acc.z); acc.w = fmaf(v0.w, c0, acc.w);
                acc.x = fmaf(v1.x, c1, acc.x); acc.y = fmaf(v1.y, c1, acc.y);
                acc.z = fmaf(v1.z, c1, acc.z); acc.w = fmaf(v1.w, c1, acc.w);
            }
            if (j < end) {
                int s0 = __ldg(&g_csr_src[j]);
                float4 v0 = __ldg(reinterpret_cast<const float4*>(x + (size_t)s0 * FIN + lane * 4));
                float c0 = SCALE_COUT ? __ldg(&g_cout[s0]) : 1.0f;
                acc.x = fmaf(v0.x, c0, acc.x); acc.y = fmaf(v0.y, c0, acc.y);
                acc.z = fmaf(v0.z, c0, acc.z); acc.w = fmaf(v0.w, c0, acc.w);
            }
            float ci = __ldg(&g_cin[gr]);
            acc.x *= ci; acc.y *= ci; acc.z *= ci; acc.w *= ci;
        }
        At[lane * 4 + 0][row] = acc.x;
        At[lane * 4 + 1][row] = acc.y;
        At[lane * 4 + 2][row] = acc.z;
        At[lane * 4 + 3][row] = acc.w;
    }
    __syncthreads();

    // ---- phase 2: packed f32x2 GEMM from smem ----
    int r0 = (tid >> 5) * 8;         // warp id * 8 (rows)
    int c0 = (tid & 31) * 4;         // lane * 4    (cols)

    u64 acc[4][4];
#pragma unroll
    for (int p = 0; p < 4; p++)
#pragma unroll
        for (int j = 0; j < 4; j++) acc[p][j] = 0ull;

    for (int k0 = 0; k0 < FIN; k0 += 16) {
        // stage W chunk (16 x 128)
#pragma unroll
        for (int t = 0; t < 2; t++) {
            int p = tid + t * 256;   // 0..511
            int k = p >> 5;          // 0..15
            int c4 = p & 31;
            *reinterpret_cast<float4*>(&Ws[k][c4 * 4]) =
                __ldg(reinterpret_cast<const float4*>(W + (size_t)(k0 + k) * 128 + c4 * 4));
        }
        __syncthreads();

#pragma unroll
        for (int kk = 0; kk < 16; kk++) {
            float4 w = *reinterpret_cast<const float4*>(&Ws[kk][c0]);
            u64 w0 = pack2(w.x, w.x);
            u64 w1 = pack2(w.y, w.y);
            u64 w2 = pack2(w.z, w.z);
            u64 w3 = pack2(w.w, w.w);
#pragma unroll
            for (int p = 0; p < 4; p++) {
                u64 a = *reinterpret_cast<const u64*>(&At[k0 + kk][r0 + 2 * p]);
                acc[p][0] = fma2(a, w0, acc[p][0]);
                acc[p][1] = fma2(a, w1, acc[p][1]);
                acc[p][2] = fma2(a, w2, acc[p][2]);
                acc[p][3] = fma2(a, w3, acc[p][3]);
            }
        }
        __syncthreads();
    }

    float b0 = bias[c0 + 0], b1 = bias[c0 + 1], b2 = bias[c0 + 2], b3 = bias[c0 + 3];
#pragma unroll
    for (int p = 0; p < 4; p++) {
        float2 a0 = unpack2(acc[p][0]);
        float2 a1 = unpack2(acc[p][1]);
        float2 a2 = unpack2(acc[p][2]);
        float2 a3 = unpack2(acc[p][3]);
#pragma unroll
        for (int h = 0; h < 2; h++) {
            int gr = rowBase + r0 + 2 * p + h;
            if (gr < N_NODES) {
                float4 v;
                v.x = (h ? a0.y : a0.x) + b0;
                v.y = (h ? a1.y : a1.x) + b1;
                v.z = (h ? a2.y : a2.x) + b2;
                v.w = (h ? a3.y : a3.x) + b3;
                if (RELU) {
                    v.x = fmaxf(v.x, 0.f); v.y = fmaxf(v.y, 0.f);
                    v.z = fmaxf(v.z, 0.f); v.w = fmaxf(v.w, 0.f);
                }
                if (SCALE_OUT) {
                    float co = __ldg(&g_cout[gr]);
                    v.x *= co; v.y *= co; v.z *= co; v.w *= co;
                }
                if (POOL) {
                    int g = __ldg(&gid[gr]);
                    red_add_v4(g_gsum + (size_t)g * 128 + c0, v);
                } else {
                    *reinterpret_cast<float4*>(C + (size_t)gr * 128 + c0) = v;
                }
            }
        }
    }
}

// ---------------- fused MLP head (16 graphs per block) -----------------------
__global__ __launch_bounds__(256)
void mlp_kernel(const float* __restrict__ fg,
                const float* __restrict__ Wl1, const float* __restrict__ bl1,
                const float* __restrict__ Wl2, const float* __restrict__ bl2,
                const float* __restrict__ Wl3, const float* __restrict__ bl3,
                float* __restrict__ out) {
    __shared__ float in_s[16][132];
    __shared__ float h_s[16][256];

    int tid = threadIdx.x;
    int gBase = blockIdx.x * 16;

    for (int idx = tid; idx < 16 * 128; idx += 256) {
        int gl = idx >> 7, f = idx & 127;
        int g = gBase + gl;
        float c = (float)g_gcnt[g];
        in_s[gl][f] = g_gsum[(size_t)g * 128 + f] / fmaxf(c, 1.0f);
    }
    for (int idx = tid; idx < 16 * 3; idx += 256) {
        int gl = idx / 3, f = idx % 3;
        in_s[gl][128 + f] = fg[(size_t)(gBase + gl) * 3 + f];
    }
    __syncthreads();

    float acc[16];
    {
        float b = bl1[tid];
#pragma unroll
        for (int g = 0; g < 16; g++) acc[g] = b;
        for (int i = 0; i < 131; i++) {
            float w = __ldg(&Wl1[(size_t)i * 256 + tid]);
#pragma unroll
            for (int g = 0; g < 16; g++) acc[g] = fmaf(in_s[g][i], w, acc[g]);
        }
#pragma unroll
        for (int g = 0; g < 16; g++) h_s[g][tid] = fmaxf(acc[g], 0.f);
    }
    __syncthreads();
    {
        float b = bl2[tid];
#pragma unroll
        for (int g = 0; g < 16; g++) acc[g] = b;
        for (int i = 0; i < 256; i++) {
            float w = __ldg(&Wl2[(size_t)i * 256 + tid]);
#pragma unroll
            for (int g = 0; g < 16; g++) acc[g] = fmaf(h_s[g][i], w, acc[g]);
        }
        __syncthreads();
#pragma unroll
        for (int g = 0; g < 16; g++) h_s[g][tid] = fmaxf(acc[g], 0.f);
    }
    __syncthreads();
    {
        int g = tid >> 4;
        int lane = tid & 15;
        float s = 0.f;
        for (int j = lane; j < 256; j += 16) s += h_s[g][j] * __ldg(&Wl3[j]);
#pragma unroll
        for (int off = 8; off > 0; off >>= 1)
            s += __shfl_down_sync(0xFFFFFFFFu, s, off, 16);
        if (lane == 0) out[gBase + g] = s + bl3[0];
    }
}

// ---------------- launch -----------------------------------------------------
extern "C" void kernel_launch(void* const* d_in, const int* in_sizes, int n_in,
                              void* d_out, int out_size) {
    const float* feats_node  = (const float*)d_in[0];
    const float* feats_graph = (const float*)d_in[1];
    const float* W1 = (const float*)d_in[2];
    const float* b1 = (const float*)d_in[3];
    const float* W2 = (const float*)d_in[4];
    const float* b2 = (const float*)d_in[5];
    const float* W3 = (const float*)d_in[6];
    const float* b3 = (const float*)d_in[7];
    const float* Wl1 = (const float*)d_in[8];
    const float* bl1 = (const float*)d_in[9];
    const float* Wl2 = (const float*)d_in[10];
    const float* bl2 = (const float*)d_in[11];
    const float* Wl3 = (const float*)d_in[12];
    const float* bl3 = (const float*)d_in[13];
    const int* src = (const int*)d_in[14];
    const int* dst = (const int*)d_in[15];
    const int* gid = (const int*)d_in[16];
    float* out = (float*)d_out;

    void *p_x, *p_y;
    cudaGetSymbolAddress(&p_x, g_x);
    cudaGetSymbolAddress(&p_y, g_y);
    float* xb = (float*)p_x;
    float* yb = (float*)p_y;

    // --- preprocessing: degrees, CSR by dst (single-pass scan), fill ---
    zero_misc_kernel<<<(N_NODES + 255) / 256, 256>>>();
    degree_kernel<<<(N_EDGES + 255) / 256, 256>>>(src, dst);
    scan_kernel<<<SCAN_NB, SCAN_BS>>>(gid);
    fill_kernel<<<(N_EDGES + 255) / 256, 256>>>(src, dst);

    const int blocks = (N_NODES + 63) / 64;

    // layer 1: aggregate feats (c_out per edge), GEMM 64->128, relu, *c_out
    gconv_kernel<IN_FEATS, true, true, true, false><<<blocks, 256>>>(feats_node, W1, b1, xb, gid);
    // layer 2: aggregate (pre-scaled), GEMM 128->128, relu, *c_out
    gconv_kernel<HIDDEN, false, true, true, false><<<blocks, 256>>>(xb, W2, b2, yb, gid);
    // layer 3: aggregate, GEMM 128->128 (no relu), fused mean-pool RED
    gconv_kernel<HIDDEN, false, false, false, true><<<blocks, 256>>>(yb, W3, b3, nullptr, gid);

    // MLP head
    mlp_kernel<<<N_GRAPHS / 16, 256>>>(feats_graph, Wl1, bl1, Wl2, bl2, Wl3, bl3, out);
}

// round 5
// speedup vs baseline: 1.1010x; 1.1010x over previous
#include <cuda_runtime.h>
#include <cuda_bf16.h>
#include <cstdint>

#define N_NODES 50000
#define N_EDGES 600000
#define N_GRAPHS 2000
#define IN_FEATS 64
#define HIDDEN 128
#define SCAN_BS 1024
#define SCAN_NB ((N_NODES + SCAN_BS - 1) / SCAN_BS)   // 49

typedef unsigned long long u64;

// ---------------- scratch (device globals; no allocation allowed) ----------
__device__ int   g_deg_out[N_NODES];
__device__ int   g_deg_in[N_NODES];
__device__ float g_cout[N_NODES];
__device__ float g_cin[N_NODES];
__device__ int   g_rowstart[N_NODES + 1];
__device__ int   g_fill[N_NODES];
__device__ int   g_scanagg[SCAN_NB];
__device__ int   g_scanflag[SCAN_NB];
__device__ int   g_csr_src[N_EDGES];
__device__ float g_agg[(size_t)N_NODES * HIDDEN];
__device__ float g_x[(size_t)N_NODES * HIDDEN];
__device__ float g_y[(size_t)N_NODES * HIDDEN];
__device__ float g_gsum[(size_t)N_GRAPHS * HIDDEN];
__device__ int   g_gcnt[N_GRAPHS];

// ---------------- helpers ---------------------------------------------------
__device__ __forceinline__ void red_add_v4(float* p, float4 v) {
    asm volatile("red.global.add.v4.f32 [%0], {%1, %2, %3, %4};"
                 :: "l"(p), "f"(v.x), "f"(v.y), "f"(v.z), "f"(v.w)
                 : "memory");
}
__device__ __forceinline__ u64 pack2(float lo, float hi) {
    u64 r; asm("mov.b64 %0, {%1, %2};" : "=l"(r) : "f"(lo), "f"(hi)); return r;
}
__device__ __forceinline__ u64 fma2(u64 a, u64 b, u64 c) {
    u64 d; asm("fma.rn.f32x2 %0, %1, %2, %3;" : "=l"(d) : "l"(a), "l"(b), "l"(c)); return d;
}
__device__ __forceinline__ float2 unpack2(u64 v) {
    float2 f; asm("mov.b64 {%0, %1}, %2;" : "=f"(f.x), "=f"(f.y) : "l"(v)); return f;
}

// ---------------- zero + degree -----------------------------------------------
__global__ void zero_misc_kernel() {
    int i = blockIdx.x * blockDim.x + threadIdx.x;
    if (i < N_NODES) { g_deg_out[i] = 0; g_deg_in[i] = 0; }
    if (i < N_GRAPHS) g_gcnt[i] = 0;
    if (i < SCAN_NB) g_scanflag[i] = 0;
}

__global__ void degree_kernel(const int* __restrict__ src, const int* __restrict__ dst) {
    int e = blockIdx.x * blockDim.x + threadIdx.x;
    if (e < N_EDGES) {
        atomicAdd(&g_deg_out[src[e]], 1);
        atomicAdd(&g_deg_in[dst[e]], 1);
    }
}

// ---------------- single-kernel scan (decoupled lookback) + finalize ---------
// 49 blocks x 1024 threads, all co-resident -> spin-wait is deadlock-free.
__global__ __launch_bounds__(SCAN_BS)
void scan_kernel(const int* __restrict__ gid) {
    int b = blockIdx.x;
    int i = b * SCAN_BS + threadIdx.x;
    int lane = threadIdx.x & 31, wid = threadIdx.x >> 5;
    int v = (i < N_NODES) ? g_deg_in[i] : 0;
    int x = v;
#pragma unroll
    for (int o = 1; o < 32; o <<= 1) {
        int y = __shfl_up_sync(0xFFFFFFFFu, x, o);
        if (lane >= o) x += y;
    }
    __shared__ int wsum[32];
    __shared__ int s_prefix;
    if (lane == 31) wsum[wid] = x;
    __syncthreads();
    if (wid == 0) {
        int w = wsum[lane];
#pragma unroll
        for (int o = 1; o < 32; o <<= 1) {
            int y = __shfl_up_sync(0xFFFFFFFFu, w, o);
            if (lane >= o) w += y;
        }
        wsum[lane] = w;
    }
    __syncthreads();
    int excl = x - v + (wid > 0 ? wsum[wid - 1] : 0);

    if (threadIdx.x == 0) {
        g_scanagg[b] = wsum[31];
        __threadfence();
        atomicExch(&g_scanflag[b], 1);
    }
    if (wid == 0) {
        int pre = 0;
        for (int base = 0; base < b; base += 32) {
            int idx = base + lane;
            int val = 0;
            if (idx < b) {
                while (atomicAdd(&g_scanflag[idx], 0) == 0) {}
                val = g_scanagg[idx];
            }
#pragma unroll
            for (int o = 16; o > 0; o >>= 1)
                val += __shfl_xor_sync(0xFFFFFFFFu, val, o);
            pre += val;
        }
        if (lane == 0) s_prefix = pre;
    }
    __syncthreads();
    int prefix = s_prefix;

    if (i < N_NODES) {
        int r = excl + prefix;
        g_rowstart[i] = r;
        g_fill[i] = r;
        g_cout[i] = rsqrtf(fmaxf((float)g_deg_out[i], 1.0f));
        g_cin[i]  = rsqrtf(fmaxf((float)g_deg_in[i], 1.0f));
        atomicAdd(&g_gcnt[gid[i]], 1);
    }
    if (i == 0) g_rowstart[N_NODES] = N_EDGES;

    // zero the pool accumulator (consumed much later by gemm3's RED)
    for (int k = b * SCAN_BS + threadIdx.x; k < N_GRAPHS * HIDDEN; k += SCAN_NB * SCAN_BS)
        g_gsum[k] = 0.0f;
}

__global__ void fill_kernel(const int* __restrict__ src, const int* __restrict__ dst) {
    int e = blockIdx.x * blockDim.x + threadIdx.x;
    if (e < N_EDGES) {
        int pos = atomicAdd(&g_fill[dst[e]], 1);
        g_csr_src[pos] = src[e];
    }
}

// ---------------- pull aggregation: agg[d] = c_in[d] * sum_{s in N(d)} x[s](*c_out[s]?)
template <int F, bool SCALE_COUT>
__global__ __launch_bounds__(256)
void pull_kernel(const float* __restrict__ x) {
    constexpr int LPN = F / 4;                 // lanes per node
    int t = blockIdx.x * blockDim.x + threadIdx.x;
    int node = t / LPN;
    int lane = t % LPN;
    if (node >= N_NODES) return;
    int j = g_rowstart[node];
    int end = g_rowstart[node + 1];
    float4 acc = make_float4(0.f, 0.f, 0.f, 0.f);
    for (; j + 1 < end; j += 2) {
        int s0 = __ldg(&g_csr_src[j]);
        int s1 = __ldg(&g_csr_src[j + 1]);
        float4 v0 = __ldg(reinterpret_cast<const float4*>(x + (size_t)s0 * F + lane * 4));
        float4 v1 = __ldg(reinterpret_cast<const float4*>(x + (size_t)s1 * F + lane * 4));
        float c0 = SCALE_COUT ? __ldg(&g_cout[s0]) : 1.0f;
        float c1 = SCALE_COUT ? __ldg(&g_cout[s1]) : 1.0f;
        acc.x = fmaf(v0.x, c0, acc.x); acc.y = fmaf(v0.y, c0, acc.y);
        acc.z = fmaf(v0.z, c0, acc.z); acc.w = fmaf(v0.w, c0, acc.w);
        acc.x = fmaf(v1.x, c1, acc.x); acc.y = fmaf(v1.y, c1, acc.y);
        acc.z = fmaf(v1.z, c1, acc.z); acc.w = fmaf(v1.w, c1, acc.w);
    }
    if (j < end) {
        int s0 = __ldg(&g_csr_src[j]);
        float4 v0 = __ldg(reinterpret_cast<const float4*>(x + (size_t)s0 * F + lane * 4));
        float c0 = SCALE_COUT ? __ldg(&g_cout[s0]) : 1.0f;
        acc.x = fmaf(v0.x, c0, acc.x); acc.y = fmaf(v0.y, c0, acc.y);
        acc.z = fmaf(v0.z, c0, acc.z); acc.w = fmaf(v0.w, c0, acc.w);
    }
    float ci = __ldg(&g_cin[node]);
    acc.x *= ci; acc.y *= ci; acc.z *= ci; acc.w *= ci;
    *reinterpret_cast<float4*>(g_agg + (size_t)node * F + lane * 4) = acc;
}

// ---------------- GEMM (packed f32x2, double-buffered W): --------------------
// C[N,128] = A[N,FIN] @ W[FIN,128] + b. BM=64, BN=128. 256 threads.
// A tile staged once (k-major), W chunks (32x128) double-buffered.
template <int FIN, bool RELU, bool SCALE_OUT, bool POOL>
__global__ __launch_bounds__(256)
void gemm_kernel(const float* __restrict__ A,
                 const float* __restrict__ W,
                 const float* __restrict__ bias,
                 float* __restrict__ C,
                 const int* __restrict__ gid) {
    __shared__ float At[FIN][66];        // k-major A tile
    __shared__ float Ws[2][32][128];     // double-buffered W chunks

    int tid = threadIdx.x;
    int rowBase = blockIdx.x * 64;
    int r0 = (tid >> 5) * 8;             // warp id * 8 (rows)
    int c0 = (tid & 31) * 4;             // lane * 4    (cols)
    constexpr int NCH = FIN / 32;        // W chunks

    // ---- stage full A tile (64 x FIN), transposed ----
    constexpr int LPN = FIN / 4;
    for (int t = tid; t < 64 * LPN; t += 256) {
        int row = t / LPN;
        int k4 = t % LPN;
        int gr = rowBase + row;
        float4 v = make_float4(0.f, 0.f, 0.f, 0.f);
        if (gr < N_NODES)
            v = __ldg(reinterpret_cast<const float4*>(A + (size_t)gr * FIN + k4 * 4));
        At[k4 * 4 + 0][row] = v.x;
        At[k4 * 4 + 1][row] = v.y;
        At[k4 * 4 + 2][row] = v.z;
        At[k4 * 4 + 3][row] = v.w;
    }
    // ---- preload W chunk 0 ----
#pragma unroll
    for (int t = 0; t < 4; t++) {
        int p = tid + t * 256;           // 0..1023
        int k = p >> 5;
        int c4 = p & 31;
        *reinterpret_cast<float4*>(&Ws[0][k][c4 * 4]) =
            __ldg(reinterpret_cast<const float4*>(W + (size_t)k * 128 + c4 * 4));
    }
    __syncthreads();

    u64 acc[4][4];
#pragma unroll
    for (int p = 0; p < 4; p++)
#pragma unroll
        for (int j = 0; j < 4; j++) acc[p][j] = 0ull;

#pragma unroll
    for (int ch = 0; ch < NCH; ch++) {
        int cur = ch & 1;
        // issue loads for next chunk first (overlap with compute)
        if (ch + 1 < NCH) {
#pragma unroll
            for (int t = 0; t < 4; t++) {
                int p = tid + t * 256;
                int k = p >> 5;
                int c4 = p & 31;
                *reinterpret_cast<float4*>(&Ws[cur ^ 1][k][c4 * 4]) =
                    __ldg(reinterpret_cast<const float4*>(
                        W + (size_t)((ch + 1) * 32 + k) * 128 + c4 * 4));
            }
        }
#pragma unroll
        for (int kk = 0; kk < 32; kk++) {
            float4 w = *reinterpret_cast<const float4*>(&Ws[cur][kk][c0]);
            u64 w0 = pack2(w.x, w.x);
            u64 w1 = pack2(w.y, w.y);
            u64 w2 = pack2(w.z, w.z);
            u64 w3 = pack2(w.w, w.w);
#pragma unroll
            for (int p = 0; p < 4; p++) {
                u64 a = *reinterpret_cast<const u64*>(&At[ch * 32 + kk][r0 + 2 * p]);
                acc[p][0] = fma2(a, w0, acc[p][0]);
                acc[p][1] = fma2(a, w1, acc[p][1]);
                acc[p][2] = fma2(a, w2, acc[p][2]);
                acc[p][3] = fma2(a, w3, acc[p][3]);
            }
        }
        if (ch + 1 < NCH) __syncthreads();
    }

    float b0 = bias[c0 + 0], b1 = bias[c0 + 1], b2 = bias[c0 + 2], b3 = bias[c0 + 3];
#pragma unroll
    for (int p = 0; p < 4; p++) {
        float2 a0 = unpack2(acc[p][0]);
        float2 a1 = unpack2(acc[p][1]);
        float2 a2 = unpack2(acc[p][2]);
        float2 a3 = unpack2(acc[p][3]);
#pragma unroll
        for (int h = 0; h < 2; h++) {
            int gr = rowBase + r0 + 2 * p + h;
            if (gr < N_NODES) {
                float4 v;
                v.x = (h ? a0.y : a0.x) + b0;
                v.y = (h ? a1.y : a1.x) + b1;
                v.z = (h ? a2.y : a2.x) + b2;
                v.w = (h ? a3.y : a3.x) + b3;
                if (RELU) {
                    v.x = fmaxf(v.x, 0.f); v.y = fmaxf(v.y, 0.f);
                    v.z = fmaxf(v.z, 0.f); v.w = fmaxf(v.w, 0.f);
                }
                if (SCALE_OUT) {
                    float co = __ldg(&g_cout[gr]);
                    v.x *= co; v.y *= co; v.z *= co; v.w *= co;
                }
                if (POOL) {
                    int g = __ldg(&gid[gr]);
                    red_add_v4(g_gsum + (size_t)g * 128 + c0, v);
                } else {
                    *reinterpret_cast<float4*>(C + (size_t)gr * 128 + c0) = v;
                }
            }
        }
    }
}

// ---------------- fused MLP head (16 graphs per block) -----------------------
__global__ __launch_bounds__(256)
void mlp_kernel(const float* __restrict__ fg,
                const float* __restrict__ Wl1, const float* __restrict__ bl1,
                const float* __restrict__ Wl2, const float* __restrict__ bl2,
                const float* __restrict__ Wl3, const float* __restrict__ bl3,
                float* __restrict__ out) {
    __shared__ float in_s[16][132];
    __shared__ float h_s[16][256];

    int tid = threadIdx.x;
    int gBase = blockIdx.x * 16;

    for (int idx = tid; idx < 16 * 128; idx += 256) {
        int gl = idx >> 7, f = idx & 127;
        int g = gBase + gl;
        float c = (float)g_gcnt[g];
        in_s[gl][f] = g_gsum[(size_t)g * 128 + f] / fmaxf(c, 1.0f);
    }
    for (int idx = tid; idx < 16 * 3; idx += 256) {
        int gl = idx / 3, f = idx % 3;
        in_s[gl][128 + f] = fg[(size_t)(gBase + gl) * 3 + f];
    }
    __syncthreads();

    float acc[16];
    {
        float b = bl1[tid];
#pragma unroll
        for (int g = 0; g < 16; g++) acc[g] = b;
        for (int i = 0; i < 131; i++) {
            float w = __ldg(&Wl1[(size_t)i * 256 + tid]);
#pragma unroll
            for (int g = 0; g < 16; g++) acc[g] = fmaf(in_s[g][i], w, acc[g]);
        }
#pragma unroll
        for (int g = 0; g < 16; g++) h_s[g][tid] = fmaxf(acc[g], 0.f);
    }
    __syncthreads();
    {
        float b = bl2[tid];
#pragma unroll
        for (int g = 0; g < 16; g++) acc[g] = b;
        for (int i = 0; i < 256; i++) {
            float w = __ldg(&Wl2[(size_t)i * 256 + tid]);
#pragma unroll
            for (int g = 0; g < 16; g++) acc[g] = fmaf(h_s[g][i], w, acc[g]);
        }
        __syncthreads();
#pragma unroll
        for (int g = 0; g < 16; g++) h_s[g][tid] = fmaxf(acc[g], 0.f);
    }
    __syncthreads();
    {
        int g = tid >> 4;
        int lane = tid & 15;
        float s = 0.f;
        for (int j = lane; j < 256; j += 16) s += h_s[g][j] * __ldg(&Wl3[j]);
#pragma unroll
        for (int off = 8; off > 0; off >>= 1)
            s += __shfl_down_sync(0xFFFFFFFFu, s, off, 16);
        if (lane == 0) out[gBase + g] = s + bl3[0];
    }
}

// ---------------- launch -----------------------------------------------------
extern "C" void kernel_launch(void* const* d_in, const int* in_sizes, int n_in,
                              void* d_out, int out_size) {
    const float* feats_node  = (const float*)d_in[0];
    const float* feats_graph = (const float*)d_in[1];
    const float* W1 = (const float*)d_in[2];
    const float* b1 = (const float*)d_in[3];
    const float* W2 = (const float*)d_in[4];
    const float* b2 = (const float*)d_in[5];
    const float* W3 = (const float*)d_in[6];
    const float* b3 = (const float*)d_in[7];
    const float* Wl1 = (const float*)d_in[8];
    const float* bl1 = (const float*)d_in[9];
    const float* Wl2 = (const float*)d_in[10];
    const float* bl2 = (const float*)d_in[11];
    const float* Wl3 = (const float*)d_in[12];
    const float* bl3 = (const float*)d_in[13];
    const int* src = (const int*)d_in[14];
    const int* dst = (const int*)d_in[15];
    const int* gid = (const int*)d_in[16];
    float* out = (float*)d_out;

    void *p_agg, *p_x, *p_y;
    cudaGetSymbolAddress(&p_agg, g_agg);
    cudaGetSymbolAddress(&p_x, g_x);
    cudaGetSymbolAddress(&p_y, g_y);
    float* agg = (float*)p_agg;
    float* xb  = (float*)p_x;
    float* yb  = (float*)p_y;

    // --- preprocessing: degrees, single-pass scan (+coeffs/gcnt/gsum-zero), fill
    zero_misc_kernel<<<(N_NODES + 255) / 256, 256>>>();
    degree_kernel<<<(N_EDGES + 255) / 256, 256>>>(src, dst);
    scan_kernel<<<SCAN_NB, SCAN_BS>>>(gid);
    fill_kernel<<<(N_EDGES + 255) / 256, 256>>>(src, dst);

    const int gemm_blocks = (N_NODES + 63) / 64;

    // ---- layer 1: pull (c_out per edge), GEMM 64->128, relu, *c_out
    pull_kernel<IN_FEATS, true><<<(N_NODES * (IN_FEATS / 4) + 255) / 256, 256>>>(feats_node);
    gemm_kernel<IN_FEATS, true, true, false><<<gemm_blocks, 256>>>(agg, W1, b1, xb, gid);

    // ---- layer 2: pull (pre-scaled), GEMM 128->128, relu, *c_out
    pull_kernel<HIDDEN, false><<<(N_NODES * (HIDDEN / 4) + 255) / 256, 256>>>(xb);
    gemm_kernel<HIDDEN, true, true, false><<<gemm_blocks, 256>>>(agg, W2, b2, yb, gid);

    // ---- layer 3: pull, GEMM 128->128 (no relu), fused mean-pool RED
    pull_kernel<HIDDEN, false><<<(N_NODES * (HIDDEN / 4) + 255) / 256, 256>>>(yb);
    gemm_kernel<HIDDEN, false, false, true><<<gemm_blocks, 256>>>(agg, W3, b3, nullptr, gid);

    // ---- MLP head ----
    mlp_kernel<<<N_GRAPHS / 16, 256>>>(feats_graph, Wl1, bl1, Wl2, bl2, Wl3, bl3, out);
}

// round 6
// speedup vs baseline: 1.2867x; 1.1686x over previous
#include <cuda_runtime.h>
#include <cuda_bf16.h>
#include <cstdint>

#define N_NODES 50000
#define N_EDGES 600000
#define N_GRAPHS 2000
#define IN_FEATS 64
#define HIDDEN 128
#define SCAN_BS 1024
#define SCAN_NB ((N_NODES + SCAN_BS - 1) / SCAN_BS)   // 49

typedef unsigned long long u64;

// ---------------- scratch (device globals; no allocation allowed) ----------
__device__ int   g_deg_out[N_NODES];
__device__ int   g_deg_in[N_NODES];
__device__ float g_cout[N_NODES];
__device__ float g_cin[N_NODES];
__device__ int   g_rowstart[N_NODES + 1];
__device__ int   g_fill[N_NODES];
__device__ int   g_scanagg[SCAN_NB];
__device__ int   g_scanflag[SCAN_NB];
__device__ int   g_csr_src[N_EDGES];
__device__ float g_agg[(size_t)N_NODES * HIDDEN];
__device__ float g_x[(size_t)N_NODES * HIDDEN];
__device__ float g_y[(size_t)N_NODES * HIDDEN];
__device__ float g_gsum[(size_t)N_GRAPHS * HIDDEN];
__device__ int   g_gcnt[N_GRAPHS];

// ---------------- helpers ---------------------------------------------------
__device__ __forceinline__ void red_add_v2(float* p, float x, float y) {
    asm volatile("red.global.add.v2.f32 [%0], {%1, %2};"
                 :: "l"(p), "f"(x), "f"(y) : "memory");
}
__device__ __forceinline__ uint32_t f2tf32(float f) {
    uint32_t u; asm("cvt.rna.tf32.f32 %0, %1;" : "=r"(u) : "f"(f)); return u;
}
__device__ __forceinline__ void mma_tf32(float& d0, float& d1, float& d2, float& d3,
                                         uint32_t a0, uint32_t a1, uint32_t a2, uint32_t a3,
                                         uint32_t b0, uint32_t b1) {
    asm volatile(
        "mma.sync.aligned.m16n8k8.row.col.f32.tf32.tf32.f32 "
        "{%0,%1,%2,%3}, {%4,%5,%6,%7}, {%8,%9}, {%0,%1,%2,%3};"
        : "+f"(d0), "+f"(d1), "+f"(d2), "+f"(d3)
        : "r"(a0), "r"(a1), "r"(a2), "r"(a3), "r"(b0), "r"(b1));
}

// ---------------- zero + degree -----------------------------------------------
__global__ void zero_misc_kernel() {
    int i = blockIdx.x * blockDim.x + threadIdx.x;
    if (i < N_NODES) { g_deg_out[i] = 0; g_deg_in[i] = 0; }
    if (i < N_GRAPHS) g_gcnt[i] = 0;
    if (i < SCAN_NB) g_scanflag[i] = 0;
}

__global__ void degree_kernel(const int* __restrict__ src, const int* __restrict__ dst) {
    int e = blockIdx.x * blockDim.x + threadIdx.x;
    if (e < N_EDGES) {
        atomicAdd(&g_deg_out[src[e]], 1);
        atomicAdd(&g_deg_in[dst[e]], 1);
    }
}

// ---------------- single-kernel scan (decoupled lookback) + finalize ---------
__global__ __launch_bounds__(SCAN_BS)
void scan_kernel(const int* __restrict__ gid) {
    int b = blockIdx.x;
    int i = b * SCAN_BS + threadIdx.x;
    int lane = threadIdx.x & 31, wid = threadIdx.x >> 5;
    int v = (i < N_NODES) ? g_deg_in[i] : 0;
    int x = v;
#pragma unroll
    for (int o = 1; o < 32; o <<= 1) {
        int y = __shfl_up_sync(0xFFFFFFFFu, x, o);
        if (lane >= o) x += y;
    }
    __shared__ int wsum[32];
    __shared__ int s_prefix;
    if (lane == 31) wsum[wid] = x;
    __syncthreads();
    if (wid == 0) {
        int w = wsum[lane];
#pragma unroll
        for (int o = 1; o < 32; o <<= 1) {
            int y = __shfl_up_sync(0xFFFFFFFFu, w, o);
            if (lane >= o) w += y;
        }
        wsum[lane] = w;
    }
    __syncthreads();
    int excl = x - v + (wid > 0 ? wsum[wid - 1] : 0);

    if (threadIdx.x == 0) {
        g_scanagg[b] = wsum[31];
        __threadfence();
        atomicExch(&g_scanflag[b], 1);
    }
    if (wid == 0) {
        int pre = 0;
        for (int base = 0; base < b; base += 32) {
            int idx = base + lane;
            int val = 0;
            if (idx < b) {
                while (atomicAdd(&g_scanflag[idx], 0) == 0) {}
                val = g_scanagg[idx];
            }
#pragma unroll
            for (int o = 16; o > 0; o >>= 1)
                val += __shfl_xor_sync(0xFFFFFFFFu, val, o);
            pre += val;
        }
        if (lane == 0) s_prefix = pre;
    }
    __syncthreads();
    int prefix = s_prefix;

    if (i < N_NODES) {
        int r = excl + prefix;
        g_rowstart[i] = r;
        g_fill[i] = r;
        g_cout[i] = rsqrtf(fmaxf((float)g_deg_out[i], 1.0f));
        g_cin[i]  = rsqrtf(fmaxf((float)g_deg_in[i], 1.0f));
        atomicAdd(&g_gcnt[gid[i]], 1);
    }
    if (i == 0) g_rowstart[N_NODES] = N_EDGES;

    for (int k = b * SCAN_BS + threadIdx.x; k < N_GRAPHS * HIDDEN; k += SCAN_NB * SCAN_BS)
        g_gsum[k] = 0.0f;
}

__global__ void fill_kernel(const int* __restrict__ src, const int* __restrict__ dst) {
    int e = blockIdx.x * blockDim.x + threadIdx.x;
    if (e < N_EDGES) {
        int pos = atomicAdd(&g_fill[dst[e]], 1);
        g_csr_src[pos] = src[e];
    }
}

// ---------------- pull aggregation: agg[d] = c_in[d] * sum_{s in N(d)} x[s](*c_out[s]?)
template <int F, bool SCALE_COUT>
__global__ __launch_bounds__(256)
void pull_kernel(const float* __restrict__ x) {
    constexpr int LPN = F / 4;
    int t = blockIdx.x * blockDim.x + threadIdx.x;
    int node = t / LPN;
    int lane = t % LPN;
    if (node >= N_NODES) return;
    int j = g_rowstart[node];
    int end = g_rowstart[node + 1];
    float4 acc = make_float4(0.f, 0.f, 0.f, 0.f);
    for (; j + 1 < end; j += 2) {
        int s0 = __ldg(&g_csr_src[j]);
        int s1 = __ldg(&g_csr_src[j + 1]);
        float4 v0 = __ldg(reinterpret_cast<const float4*>(x + (size_t)s0 * F + lane * 4));
        float4 v1 = __ldg(reinterpret_cast<const float4*>(x + (size_t)s1 * F + lane * 4));
        float c0 = SCALE_COUT ? __ldg(&g_cout[s0]) : 1.0f;
        float c1 = SCALE_COUT ? __ldg(&g_cout[s1]) : 1.0f;
        acc.x = fmaf(v0.x, c0, acc.x); acc.y = fmaf(v0.y, c0, acc.y);
        acc.z = fmaf(v0.z, c0, acc.z); acc.w = fmaf(v0.w, c0, acc.w);
        acc.x = fmaf(v1.x, c1, acc.x); acc.y = fmaf(v1.y, c1, acc.y);
        acc.z = fmaf(v1.z, c1, acc.z); acc.w = fmaf(v1.w, c1, acc.w);
    }
    if (j < end) {
        int s0 = __ldg(&g_csr_src[j]);
        float4 v0 = __ldg(reinterpret_cast<const float4*>(x + (size_t)s0 * F + lane * 4));
        float c0 = SCALE_COUT ? __ldg(&g_cout[s0]) : 1.0f;
        acc.x = fmaf(v0.x, c0, acc.x); acc.y = fmaf(v0.y, c0, acc.y);
        acc.z = fmaf(v0.z, c0, acc.z); acc.w = fmaf(v0.w, c0, acc.w);
    }
    float ci = __ldg(&g_cin[node]);
    acc.x *= ci; acc.y *= ci; acc.z *= ci; acc.w *= ci;
    *reinterpret_cast<float4*>(g_agg + (size_t)node * F + lane * 4) = acc;
}

// ---------------- tensor-core GEMM (tf32 mma.sync): --------------------------
// C[N,128] = A[N,FIN] @ W[FIN,128] + b. BM=64, BN=128, 256 threads (8 warps).
// Warp w: M-tile = (w%4)*16, N-range = (w/4)*64, covering 8 n8-tiles.
// Smem (dynamic, tf32 u32): At[64][FIN+4], Ws[2][32][136].
template <int FIN, bool RELU, bool SCALE_OUT, bool POOL>
__global__ __launch_bounds__(256)
void gemm_tc_kernel(const float* __restrict__ A,
                    const float* __restrict__ W,
                    const float* __restrict__ bias,
                    float* __restrict__ C,
                    const int* __restrict__ gid) {
    extern __shared__ uint32_t smem[];
    constexpr int KPAD = FIN + 4;          // (FIN+4) mod 32 == 4 -> conflict-free A frags
    constexpr int NPAD = 136;              // 136 mod 32 == 8 -> conflict-free B frags
    constexpr int NCH = FIN / 32;
    uint32_t* At = smem;                   // 64 * KPAD
    uint32_t* Ws = smem + 64 * KPAD;       // 2 * 32 * NPAD

    int tid = threadIdx.x;
    int warp = tid >> 5;
    int lane = tid & 31;
    int rowBase = blockIdx.x * 64;

    // ---- stage A tile (64 x FIN), convert to tf32 ----
    constexpr int LPN = FIN / 4;
    for (int t = tid; t < 64 * LPN; t += 256) {
        int row = t / LPN;
        int k4 = t % LPN;
        int gr = rowBase + row;
        float4 v = make_float4(0.f, 0.f, 0.f, 0.f);
        if (gr < N_NODES)
            v = __ldg(reinterpret_cast<const float4*>(A + (size_t)gr * FIN + k4 * 4));
        uint4 u;
        u.x = f2tf32(v.x); u.y = f2tf32(v.y); u.z = f2tf32(v.z); u.w = f2tf32(v.w);
        *reinterpret_cast<uint4*>(At + row * KPAD + k4 * 4) = u;
    }
    // ---- preload W chunk 0 (32x128), convert to tf32 ----
#pragma unroll
    for (int t = 0; t < 4; t++) {
        int p = tid + t * 256;
        int k = p >> 5;
        int c4 = p & 31;
        float4 w = __ldg(reinterpret_cast<const float4*>(W + (size_t)k * 128 + c4 * 4));
        uint4 u;
        u.x = f2tf32(w.x); u.y = f2tf32(w.y); u.z = f2tf32(w.z); u.w = f2tf32(w.w);
        *reinterpret_cast<uint4*>(Ws + k * NPAD + c4 * 4) = u;
    }
    __syncthreads();

    int m0 = (warp & 3) * 16;
    int n0 = (warp >> 2) * 64;
    int lq = lane & 3;                 // thread-in-group (k / col-pair index)
    int lg = lane >> 2;                // group id (row / n index)

    float acc[8][4];
#pragma unroll
    for (int nt = 0; nt < 8; nt++)
#pragma unroll
        for (int j = 0; j < 4; j++) acc[nt][j] = 0.f;

    const uint32_t* arow0 = At + (m0 + lg) * KPAD + lq;
    const uint32_t* arow1 = arow0 + 8 * KPAD;

#pragma unroll
    for (int ch = 0; ch < NCH; ch++) {
        int cur = ch & 1;
        // prefetch next W chunk
        if (ch + 1 < NCH) {
#pragma unroll
            for (int t = 0; t < 4; t++) {
                int p = tid + t * 256;
                int k = p >> 5;
                int c4 = p & 31;
                float4 w = __ldg(reinterpret_cast<const float4*>(
                    W + (size_t)((ch + 1) * 32 + k) * 128 + c4 * 4));
                uint4 u;
                u.x = f2tf32(w.x); u.y = f2tf32(w.y); u.z = f2tf32(w.z); u.w = f2tf32(w.w);
                *reinterpret_cast<uint4*>(Ws + (cur ^ 1) * 32 * NPAD + k * NPAD + c4 * 4) = u;
            }
        }
        const uint32_t* wsb = Ws + cur * 32 * NPAD;
#pragma unroll
        for (int ks = 0; ks < 4; ks++) {
            int kb = ch * 32 + ks * 8;
            uint32_t a0 = arow0[kb];
            uint32_t a1 = arow1[kb];
            uint32_t a2 = arow0[kb + 4];
            uint32_t a3 = arow1[kb + 4];
            const uint32_t* b0row = wsb + (ks * 8 + lq) * NPAD + n0 + lg;
            const uint32_t* b1row = b0row + 4 * NPAD;
#pragma unroll
            for (int nt = 0; nt < 8; nt++) {
                uint32_t b0 = b0row[nt * 8];
                uint32_t b1 = b1row[nt * 8];
                mma_tf32(acc[nt][0], acc[nt][1], acc[nt][2], acc[nt][3],
                         a0, a1, a2, a3, b0, b1);
            }
        }
        if (ch + 1 < NCH) __syncthreads();
    }

    // ---- epilogue ----
    int r_lo = rowBase + m0 + lg;
    int r_hi = r_lo + 8;
    float co_lo = 1.f, co_hi = 1.f;
    if (SCALE_OUT) {
        if (r_lo < N_NODES) co_lo = __ldg(&g_cout[r_lo]);
        if (r_hi < N_NODES) co_hi = __ldg(&g_cout[r_hi]);
    }
    int g_lo = 0, g_hi = 0;
    if (POOL) {
        if (r_lo < N_NODES) g_lo = __ldg(&gid[r_lo]);
        if (r_hi < N_NODES) g_hi = __ldg(&gid[r_hi]);
    }
#pragma unroll
    for (int nt = 0; nt < 8; nt++) {
        int col = n0 + nt * 8 + 2 * lq;
        float2 bb = __ldg(reinterpret_cast<const float2*>(bias + col));
        float v0 = acc[nt][0] + bb.x, v1 = acc[nt][1] + bb.y;
        float v2 = acc[nt][2] + bb.x, v3 = acc[nt][3] + bb.y;
        if (RELU) {
            v0 = fmaxf(v0, 0.f); v1 = fmaxf(v1, 0.f);
            v2 = fmaxf(v2, 0.f); v3 = fmaxf(v3, 0.f);
        }
        if (SCALE_OUT) { v0 *= co_lo; v1 *= co_lo; v2 *= co_hi; v3 *= co_hi; }
        if (r_lo < N_NODES) {
            if (POOL) red_add_v2(g_gsum + (size_t)g_lo * 128 + col, v0, v1);
            else *reinterpret_cast<float2*>(C + (size_t)r_lo * 128 + col) = make_float2(v0, v1);
        }
        if (r_hi < N_NODES) {
            if (POOL) red_add_v2(g_gsum + (size_t)g_hi * 128 + col, v2, v3);
            else *reinterpret_cast<float2*>(C + (size_t)r_hi * 128 + col) = make_float2(v2, v3);
        }
    }
}

// ---------------- fused MLP head (16 graphs per block) -----------------------
__global__ __launch_bounds__(256)
void mlp_kernel(const float* __restrict__ fg,
                const float* __restrict__ Wl1, const float* __restrict__ bl1,
                const float* __restrict__ Wl2, const float* __restrict__ bl2,
                const float* __restrict__ Wl3, const float* __restrict__ bl3,
                float* __restrict__ out) {
    __shared__ float in_s[16][132];
    __shared__ float h_s[16][256];

    int tid = threadIdx.x;
    int gBase = blockIdx.x * 16;

    for (int idx = tid; idx < 16 * 128; idx += 256) {
        int gl = idx >> 7, f = idx & 127;
        int g = gBase + gl;
        float c = (float)g_gcnt[g];
        in_s[gl][f] = g_gsum[(size_t)g * 128 + f] / fmaxf(c, 1.0f);
    }
    for (int idx = tid; idx < 16 * 3; idx += 256) {
        int gl = idx / 3, f = idx % 3;
        in_s[gl][128 + f] = fg[(size_t)(gBase + gl) * 3 + f];
    }
    __syncthreads();

    float acc[16];
    {
        float b = bl1[tid];
#pragma unroll
        for (int g = 0; g < 16; g++) acc[g] = b;
        for (int i = 0; i < 131; i++) {
            float w = __ldg(&Wl1[(size_t)i * 256 + tid]);
#pragma unroll
            for (int g = 0; g < 16; g++) acc[g] = fmaf(in_s[g][i], w, acc[g]);
        }
#pragma unroll
        for (int g = 0; g < 16; g++) h_s[g][tid] = fmaxf(acc[g], 0.f);
    }
    __syncthreads();
    {
        float b = bl2[tid];
#pragma unroll
        for (int g = 0; g < 16; g++) acc[g] = b;
        for (int i = 0; i < 256; i++) {
            float w = __ldg(&Wl2[(size_t)i * 256 + tid]);
#pragma unroll
            for (int g = 0; g < 16; g++) acc[g] = fmaf(h_s[g][i], w, acc[g]);
        }
        __syncthreads();
#pragma unroll
        for (int g = 0; g < 16; g++) h_s[g][tid] = fmaxf(acc[g], 0.f);
    }
    __syncthreads();
    {
        int g = tid >> 4;
        int lane = tid & 15;
        float s = 0.f;
        for (int j = lane; j < 256; j += 16) s += h_s[g][j] * __ldg(&Wl3[j]);
#pragma unroll
        for (int off = 8; off > 0; off >>= 1)
            s += __shfl_down_sync(0xFFFFFFFFu, s, off, 16);
        if (lane == 0) out[gBase + g] = s + bl3[0];
    }
}

// ---------------- launch -----------------------------------------------------
extern "C" void kernel_launch(void* const* d_in, const int* in_sizes, int n_in,
                              void* d_out, int out_size) {
    const float* feats_node  = (const float*)d_in[0];
    const float* feats_graph = (const float*)d_in[1];
    const float* W1 = (const float*)d_in[2];
    const float* b1 = (const float*)d_in[3];
    const float* W2 = (const float*)d_in[4];
    const float* b2 = (const float*)d_in[5];
    const float* W3 = (const float*)d_in[6];
    const float* b3 = (const float*)d_in[7];
    const float* Wl1 = (const float*)d_in[8];
    const float* bl1 = (const float*)d_in[9];
    const float* Wl2 = (const float*)d_in[10];
    const float* bl2 = (const float*)d_in[11];
    const float* Wl3 = (const float*)d_in[12];
    const float* bl3 = (const float*)d_in[13];
    const int* src = (const int*)d_in[14];
    const int* dst = (const int*)d_in[15];
    const int* gid = (const int*)d_in[16];
    float* out = (float*)d_out;

    void *p_agg, *p_x, *p_y;
    cudaGetSymbolAddress(&p_agg, g_agg);
    cudaGetSymbolAddress(&p_x, g_x);
    cudaGetSymbolAddress(&p_y, g_y);
    float* agg = (float*)p_agg;
    float* xb  = (float*)p_x;
    float* yb  = (float*)p_y;

    // dynamic smem sizes for the tensor-core GEMMs
    const int SMEM64  = (64 * (IN_FEATS + 4) + 2 * 32 * 136) * 4;   // 52224
    const int SMEM128 = (64 * (HIDDEN + 4)   + 2 * 32 * 136) * 4;   // 68608
    cudaFuncSetAttribute(gemm_tc_kernel<IN_FEATS, true, true, false>,
                         cudaFuncAttributeMaxDynamicSharedMemorySize, SMEM64);
    cudaFuncSetAttribute(gemm_tc_kernel<HIDDEN, true, true, false>,
                         cudaFuncAttributeMaxDynamicSharedMemorySize, SMEM128);
    cudaFuncSetAttribute(gemm_tc_kernel<HIDDEN, false, false, true>,
                         cudaFuncAttributeMaxDynamicSharedMemorySize, SMEM128);

    // --- preprocessing: degrees, single-pass scan (+coeffs/gcnt/gsum-zero), fill
    zero_misc_kernel<<<(N_NODES + 255) / 256, 256>>>();
    degree_kernel<<<(N_EDGES + 255) / 256, 256>>>(src, dst);
    scan_kernel<<<SCAN_NB, SCAN_BS>>>(gid);
    fill_kernel<<<(N_EDGES + 255) / 256, 256>>>(src, dst);

    const int gemm_blocks = (N_NODES + 63) / 64;

    // ---- layer 1: pull (c_out per edge), GEMM 64->128, relu, *c_out
    pull_kernel<IN_FEATS, true><<<(N_NODES * (IN_FEATS / 4) + 255) / 256, 256>>>(feats_node);
    gemm_tc_kernel<IN_FEATS, true, true, false><<<gemm_blocks, 256, SMEM64>>>(agg, W1, b1, xb, gid);

    // ---- layer 2: pull (pre-scaled), GEMM 128->128, relu, *c_out
    pull_kernel<HIDDEN, false><<<(N_NODES * (HIDDEN / 4) + 255) / 256, 256>>>(xb);
    gemm_tc_kernel<HIDDEN, true, true, false><<<gemm_blocks, 256, SMEM128>>>(agg, W2, b2, yb, gid);

    // ---- layer 3: pull, GEMM 128->128 (no relu), fused mean-pool RED
    pull_kernel<HIDDEN, false><<<(N_NODES * (HIDDEN / 4) + 255) / 256, 256>>>(yb);
    gemm_tc_kernel<HIDDEN, false, false, true><<<gemm_blocks, 256, SMEM128>>>(agg, W3, b3, nullptr, gid);

    // ---- MLP head ----
    mlp_kernel<<<N_GRAPHS / 16, 256>>>(feats_graph, Wl1, bl1, Wl2, bl2, Wl3, bl3, out);
}

// round 7
// speedup vs baseline: 1.4007x; 1.0886x over previous
#include <cuda_runtime.h>
#include <cuda_bf16.h>
#include <cstdint>

#define N_NODES 50000
#define N_EDGES 600000
#define N_GRAPHS 2000
#define IN_FEATS 64
#define HIDDEN 128
#define SCAN_BS 1024
#define SCAN_NB ((N_NODES + SCAN_BS - 1) / SCAN_BS)   // 49
#define E_HALF ((N_EDGES + 1) / 2)

typedef unsigned long long u64;

// ---------------- scratch (device globals; no allocation allowed) ----------
__device__ int   g_deg_out[N_NODES];
__device__ int   g_deg_in[N_NODES];
__device__ float g_cout[N_NODES];
__device__ float g_cin[N_NODES];
__device__ int   g_rowstart[N_NODES + 1];
__device__ int   g_fill[N_NODES];
__device__ int   g_scanagg[SCAN_NB];
__device__ int   g_scanflag[SCAN_NB];
__device__ int   g_csr_src[N_EDGES];
__device__ float g_agg[(size_t)N_NODES * HIDDEN];
__device__ __nv_bfloat16 g_f16[(size_t)N_NODES * IN_FEATS];  // feats * c_out, bf16
__device__ __nv_bfloat16 g_x16[(size_t)N_NODES * HIDDEN];    // layer1 out * c_out
__device__ __nv_bfloat16 g_y16[(size_t)N_NODES * HIDDEN];    // layer2 out * c_out
__device__ float g_gsum[(size_t)N_GRAPHS * HIDDEN];
__device__ int   g_gcnt[N_GRAPHS];

// ---------------- helpers ---------------------------------------------------
__device__ __forceinline__ void red_add_v2(float* p, float x, float y) {
    asm volatile("red.global.add.v2.f32 [%0], {%1, %2};"
                 :: "l"(p), "f"(x), "f"(y) : "memory");
}
__device__ __forceinline__ uint32_t f2tf32(float f) {
    uint32_t u; asm("cvt.rna.tf32.f32 %0, %1;" : "=r"(u) : "f"(f)); return u;
}
__device__ __forceinline__ void mma_tf32(float& d0, float& d1, float& d2, float& d3,
                                         uint32_t a0, uint32_t a1, uint32_t a2, uint32_t a3,
                                         uint32_t b0, uint32_t b1) {
    asm volatile(
        "mma.sync.aligned.m16n8k8.row.col.f32.tf32.tf32.f32 "
        "{%0,%1,%2,%3}, {%4,%5,%6,%7}, {%8,%9}, {%0,%1,%2,%3};"
        : "+f"(d0), "+f"(d1), "+f"(d2), "+f"(d3)
        : "r"(a0), "r"(a1), "r"(a2), "r"(a3), "r"(b0), "r"(b1));
}
__device__ __forceinline__ float2 bf2f2(uint32_t u) {
    __nv_bfloat162 h = *reinterpret_cast<__nv_bfloat162*>(&u);
    return __bfloat1622float2(h);
}

// ---------------- zero + degree -----------------------------------------------
__global__ void zero_misc_kernel() {
    int i = blockIdx.x * blockDim.x + threadIdx.x;
    if (i < N_NODES) { g_deg_out[i] = 0; g_deg_in[i] = 0; }
    if (i < N_GRAPHS) g_gcnt[i] = 0;
    if (i < SCAN_NB) g_scanflag[i] = 0;
}

__global__ void degree_kernel(const int* __restrict__ src, const int* __restrict__ dst) {
    int e = blockIdx.x * blockDim.x + threadIdx.x;
    if (e < E_HALF) {
        int s0 = src[e], d0 = dst[e];
        int eb = e + E_HALF;
        int s1 = -1, d1 = -1;
        if (eb < N_EDGES) { s1 = src[eb]; d1 = dst[eb]; }
        atomicAdd(&g_deg_out[s0], 1);
        if (s1 >= 0) atomicAdd(&g_deg_out[s1], 1);
        atomicAdd(&g_deg_in[d0], 1);
        if (d1 >= 0) atomicAdd(&g_deg_in[d1], 1);
    }
}

// ---------------- single-kernel scan (decoupled lookback) + finalize ---------
// Also converts feats_node -> bf16 pre-scaled by c_out.
__global__ __launch_bounds__(SCAN_BS)
void scan_kernel(const int* __restrict__ gid, const float* __restrict__ feats) {
    int b = blockIdx.x;
    int i = b * SCAN_BS + threadIdx.x;
    int lane = threadIdx.x & 31, wid = threadIdx.x >> 5;
    int v = (i < N_NODES) ? g_deg_in[i] : 0;
    int x = v;
#pragma unroll
    for (int o = 1; o < 32; o <<= 1) {
        int y = __shfl_up_sync(0xFFFFFFFFu, x, o);
        if (lane >= o) x += y;
    }
    __shared__ int wsum[32];
    __shared__ int s_prefix;
    if (lane == 31) wsum[wid] = x;
    __syncthreads();
    if (wid == 0) {
        int w = wsum[lane];
#pragma unroll
        for (int o = 1; o < 32; o <<= 1) {
            int y = __shfl_up_sync(0xFFFFFFFFu, w, o);
            if (lane >= o) w += y;
        }
        wsum[lane] = w;
    }
    __syncthreads();
    int excl = x - v + (wid > 0 ? wsum[wid - 1] : 0);

    if (threadIdx.x == 0) {
        g_scanagg[b] = wsum[31];
        __threadfence();
        atomicExch(&g_scanflag[b], 1);
    }
    if (wid == 0) {
        int pre = 0;
        for (int base = 0; base < b; base += 32) {
            int idx = base + lane;
            int val = 0;
            if (idx < b) {
                while (atomicAdd(&g_scanflag[idx], 0) == 0) {}
                val = g_scanagg[idx];
            }
#pragma unroll
            for (int o = 16; o > 0; o >>= 1)
                val += __shfl_xor_sync(0xFFFFFFFFu, val, o);
            pre += val;
        }
        if (lane == 0) s_prefix = pre;
    }
    __syncthreads();
    int prefix = s_prefix;

    float my_cout = 0.f;
    if (i < N_NODES) {
        int r = excl + prefix;
        g_rowstart[i] = r;
        g_fill[i] = r;
        my_cout = rsqrtf(fmaxf((float)g_deg_out[i], 1.0f));
        g_cout[i] = my_cout;
        g_cin[i]  = rsqrtf(fmaxf((float)g_deg_in[i], 1.0f));
        atomicAdd(&g_gcnt[gid[i]], 1);
    }
    if (i == 0) g_rowstart[N_NODES] = N_EDGES;
    __syncthreads();   // g_cout for this block's node range now visible

    // convert this block's feats rows to bf16, pre-scaled by c_out (coalesced)
    constexpr int CPN = IN_FEATS / 4;   // float4 chunks per node (16)
    int nodeBase = b * SCAN_BS;
    for (int idx = threadIdx.x; idx < SCAN_BS * CPN; idx += SCAN_BS) {
        int node = nodeBase + idx / CPN;
        int l4 = idx % CPN;
        if (node < N_NODES) {
            float co = g_cout[node];
            float4 fv = __ldg(reinterpret_cast<const float4*>(
                feats + (size_t)node * IN_FEATS + l4 * 4));
            __nv_bfloat162 h0 = __floats2bfloat162_rn(fv.x * co, fv.y * co);
            __nv_bfloat162 h1 = __floats2bfloat162_rn(fv.z * co, fv.w * co);
            uint2 st;
            st.x = *reinterpret_cast<uint32_t*>(&h0);
            st.y = *reinterpret_cast<uint32_t*>(&h1);
            *reinterpret_cast<uint2*>(g_f16 + (size_t)node * IN_FEATS + l4 * 4) = st;
        }
    }

    // zero the pool accumulator (consumed much later by gemm3's RED)
    for (int k = b * SCAN_BS + threadIdx.x; k < N_GRAPHS * HIDDEN; k += SCAN_NB * SCAN_BS)
        g_gsum[k] = 0.0f;
}

__global__ void fill_kernel(const int* __restrict__ src, const int* __restrict__ dst) {
    int e = blockIdx.x * blockDim.x + threadIdx.x;
    if (e < E_HALF) {
        int d0 = dst[e], s0 = src[e];
        int eb = e + E_HALF;
        int d1 = -1, s1 = 0;
        if (eb < N_EDGES) { d1 = dst[eb]; s1 = src[eb]; }
        int p0 = atomicAdd(&g_fill[d0], 1);
        int p1 = (d1 >= 0) ? atomicAdd(&g_fill[d1], 1) : 0;
        g_csr_src[p0] = s0;
        if (d1 >= 0) g_csr_src[p1] = s1;
    }
}

// ---------------- bf16 pull aggregation --------------------------------------
// agg[d] = c_in[d] * sum_{s in N(d)} x16[s]   (x16 already carries c_out)
// Each lane handles 8 bf16 features (one uint4 = 16B per edge).
template <int F>
__global__ __launch_bounds__(256)
void pull_bf16_kernel(const __nv_bfloat16* __restrict__ x16) {
    constexpr int LPN = F / 8;                 // lanes per node
    int t = blockIdx.x * blockDim.x + threadIdx.x;
    int node = t / LPN;
    int lane = t % LPN;
    if (node >= N_NODES) return;
    int j = g_rowstart[node];
    int end = g_rowstart[node + 1];
    float2 a0 = make_float2(0.f, 0.f), a1 = a0, a2 = a0, a3 = a0;
    for (; j + 1 < end; j += 2) {
        int s0 = __ldg(&g_csr_src[j]);
        int s1 = __ldg(&g_csr_src[j + 1]);
        uint4 u0 = __ldg(reinterpret_cast<const uint4*>(x16 + (size_t)s0 * F + lane * 8));
        uint4 u1 = __ldg(reinterpret_cast<const uint4*>(x16 + (size_t)s1 * F + lane * 8));
        float2 f;
        f = bf2f2(u0.x); a0.x += f.x; a0.y += f.y;
        f = bf2f2(u0.y); a1.x += f.x; a1.y += f.y;
        f = bf2f2(u0.z); a2.x += f.x; a2.y += f.y;
        f = bf2f2(u0.w); a3.x += f.x; a3.y += f.y;
        f = bf2f2(u1.x); a0.x += f.x; a0.y += f.y;
        f = bf2f2(u1.y); a1.x += f.x; a1.y += f.y;
        f = bf2f2(u1.z); a2.x += f.x; a2.y += f.y;
        f = bf2f2(u1.w); a3.x += f.x; a3.y += f.y;
    }
    if (j < end) {
        int s0 = __ldg(&g_csr_src[j]);
        uint4 u0 = __ldg(reinterpret_cast<const uint4*>(x16 + (size_t)s0 * F + lane * 8));
        float2 f;
        f = bf2f2(u0.x); a0.x += f.x; a0.y += f.y;
        f = bf2f2(u0.y); a1.x += f.x; a1.y += f.y;
        f = bf2f2(u0.z); a2.x += f.x; a2.y += f.y;
        f = bf2f2(u0.w); a3.x += f.x; a3.y += f.y;
    }
    float ci = __ldg(&g_cin[node]);
    float4 o0 = make_float4(a0.x * ci, a0.y * ci, a1.x * ci, a1.y * ci);
    float4 o1 = make_float4(a2.x * ci, a2.y * ci, a3.x * ci, a3.y * ci);
    float* dst = g_agg + (size_t)node * F + lane * 8;
    *reinterpret_cast<float4*>(dst) = o0;
    *reinterpret_cast<float4*>(dst + 4) = o1;
}

// ---------------- tensor-core GEMM (tf32 mma.sync): --------------------------
// C[N,128] = A[N,FIN] @ W[FIN,128] + b. BM=64, BN=128, 256 threads (8 warps).
// Non-POOL: writes bf16 output pre-scaled by c_out. POOL: fp32 RED into g_gsum.
template <int FIN, bool RELU, bool SCALE_OUT, bool POOL>
__global__ __launch_bounds__(256)
void gemm_tc_kernel(const float* __restrict__ A,
                    const float* __restrict__ W,
                    const float* __restrict__ bias,
                    __nv_bfloat16* __restrict__ C16,
                    const int* __restrict__ gid) {
    extern __shared__ uint32_t smem[];
    constexpr int KPAD = FIN + 4;
    constexpr int NPAD = 136;
    constexpr int NCH = FIN / 32;
    uint32_t* At = smem;                   // 64 * KPAD
    uint32_t* Ws = smem + 64 * KPAD;       // 2 * 32 * NPAD

    int tid = threadIdx.x;
    int warp = tid >> 5;
    int lane = tid & 31;
    int rowBase = blockIdx.x * 64;

    // ---- stage A tile (64 x FIN), convert to tf32 ----
    constexpr int LPN = FIN / 4;
    for (int t = tid; t < 64 * LPN; t += 256) {
        int row = t / LPN;
        int k4 = t % LPN;
        int gr = rowBase + row;
        float4 v = make_float4(0.f, 0.f, 0.f, 0.f);
        if (gr < N_NODES)
            v = __ldg(reinterpret_cast<const float4*>(A + (size_t)gr * FIN + k4 * 4));
        uint4 u;
        u.x = f2tf32(v.x); u.y = f2tf32(v.y); u.z = f2tf32(v.z); u.w = f2tf32(v.w);
        *reinterpret_cast<uint4*>(At + row * KPAD + k4 * 4) = u;
    }
#pragma unroll
    for (int t = 0; t < 4; t++) {
        int p = tid + t * 256;
        int k = p >> 5;
        int c4 = p & 31;
        float4 w = __ldg(reinterpret_cast<const float4*>(W + (size_t)k * 128 + c4 * 4));
        uint4 u;
        u.x = f2tf32(w.x); u.y = f2tf32(w.y); u.z = f2tf32(w.z); u.w = f2tf32(w.w);
        *reinterpret_cast<uint4*>(Ws + k * NPAD + c4 * 4) = u;
    }
    __syncthreads();

    int m0 = (warp & 3) * 16;
    int n0 = (warp >> 2) * 64;
    int lq = lane & 3;
    int lg = lane >> 2;

    float acc[8][4];
#pragma unroll
    for (int nt = 0; nt < 8; nt++)
#pragma unroll
        for (int j = 0; j < 4; j++) acc[nt][j] = 0.f;

    const uint32_t* arow0 = At + (m0 + lg) * KPAD + lq;
    const uint32_t* arow1 = arow0 + 8 * KPAD;

#pragma unroll
    for (int ch = 0; ch < NCH; ch++) {
        int cur = ch & 1;
        if (ch + 1 < NCH) {
#pragma unroll
            for (int t = 0; t < 4; t++) {
                int p = tid + t * 256;
                int k = p >> 5;
                int c4 = p & 31;
                float4 w = __ldg(reinterpret_cast<const float4*>(
                    W + (size_t)((ch + 1) * 32 + k) * 128 + c4 * 4));
                uint4 u;
                u.x = f2tf32(w.x); u.y = f2tf32(w.y); u.z = f2tf32(w.z); u.w = f2tf32(w.w);
                *reinterpret_cast<uint4*>(Ws + (cur ^ 1) * 32 * NPAD + k * NPAD + c4 * 4) = u;
            }
        }
        const uint32_t* wsb = Ws + cur * 32 * NPAD;
#pragma unroll
        for (int ks = 0; ks < 4; ks++) {
            int kb = ch * 32 + ks * 8;
            uint32_t a0 = arow0[kb];
            uint32_t a1 = arow1[kb];
            uint32_t a2 = arow0[kb + 4];
            uint32_t a3 = arow1[kb + 4];
            const uint32_t* b0row = wsb + (ks * 8 + lq) * NPAD + n0 + lg;
            const uint32_t* b1row = b0row + 4 * NPAD;
#pragma unroll
            for (int nt = 0; nt < 8; nt++) {
                uint32_t b0 = b0row[nt * 8];
                uint32_t b1 = b1row[nt * 8];
                mma_tf32(acc[nt][0], acc[nt][1], acc[nt][2], acc[nt][3],
                         a0, a1, a2, a3, b0, b1);
            }
        }
        if (ch + 1 < NCH) __syncthreads();
    }

    // ---- epilogue ----
    int r_lo = rowBase + m0 + lg;
    int r_hi = r_lo + 8;
    float co_lo = 1.f, co_hi = 1.f;
    if (SCALE_OUT) {
        if (r_lo < N_NODES) co_lo = __ldg(&g_cout[r_lo]);
        if (r_hi < N_NODES) co_hi = __ldg(&g_cout[r_hi]);
    }
    int g_lo = 0, g_hi = 0;
    if (POOL) {
        if (r_lo < N_NODES) g_lo = __ldg(&gid[r_lo]);
        if (r_hi < N_NODES) g_hi = __ldg(&gid[r_hi]);
    }
#pragma unroll
    for (int nt = 0; nt < 8; nt++) {
        int col = n0 + nt * 8 + 2 * lq;
        float2 bb = __ldg(reinterpret_cast<const float2*>(bias + col));
        float v0 = acc[nt][0] + bb.x, v1 = acc[nt][1] + bb.y;
        float v2 = acc[nt][2] + bb.x, v3 = acc[nt][3] + bb.y;
        if (RELU) {
            v0 = fmaxf(v0, 0.f); v1 = fmaxf(v1, 0.f);
            v2 = fmaxf(v2, 0.f); v3 = fmaxf(v3, 0.f);
        }
        if (SCALE_OUT) { v0 *= co_lo; v1 *= co_lo; v2 *= co_hi; v3 *= co_hi; }
        if (r_lo < N_NODES) {
            if (POOL) {
                red_add_v2(g_gsum + (size_t)g_lo * 128 + col, v0, v1);
            } else {
                __nv_bfloat162 h = __floats2bfloat162_rn(v0, v1);
                *reinterpret_cast<__nv_bfloat162*>(C16 + (size_t)r_lo * 128 + col) = h;
            }
        }
        if (r_hi < N_NODES) {
            if (POOL) {
                red_add_v2(g_gsum + (size_t)g_hi * 128 + col, v2, v3);
            } else {
                __nv_bfloat162 h = __floats2bfloat162_rn(v2, v3);
                *reinterpret_cast<__nv_bfloat162*>(C16 + (size_t)r_hi * 128 + col) = h;
            }
        }
    }
}

// ---------------- fused MLP head (16 graphs per block) -----------------------
__global__ __launch_bounds__(256)
void mlp_kernel(const float* __restrict__ fg,
                const float* __restrict__ Wl1, const float* __restrict__ bl1,
                const float* __restrict__ Wl2, const float* __restrict__ bl2,
                const float* __restrict__ Wl3, const float* __restrict__ bl3,
                float* __restrict__ out) {
    __shared__ float in_s[16][132];
    __shared__ float h_s[16][256];

    int tid = threadIdx.x;
    int gBase = blockIdx.x * 16;

    for (int idx = tid; idx < 16 * 128; idx += 256) {
        int gl = idx >> 7, f = idx & 127;
        int g = gBase + gl;
        float c = (float)g_gcnt[g];
        in_s[gl][f] = g_gsum[(size_t)g * 128 + f] / fmaxf(c, 1.0f);
    }
    for (int idx = tid; idx < 16 * 3; idx += 256) {
        int gl = idx / 3, f = idx % 3;
        in_s[gl][128 + f] = fg[(size_t)(gBase + gl) * 3 + f];
    }
    __syncthreads();

    float acc[16];
    {
        float b = bl1[tid];
#pragma unroll
        for (int g = 0; g < 16; g++) acc[g] = b;
        for (int i = 0; i < 131; i++) {
            float w = __ldg(&Wl1[(size_t)i * 256 + tid]);
#pragma unroll
            for (int g = 0; g < 16; g++) acc[g] = fmaf(in_s[g][i], w, acc[g]);
        }
#pragma unroll
        for (int g = 0; g < 16; g++) h_s[g][tid] = fmaxf(acc[g], 0.f);
    }
    __syncthreads();
    {
        float b = bl2[tid];
#pragma unroll
        for (int g = 0; g < 16; g++) acc[g] = b;
        for (int i = 0; i < 256; i++) {
            float w = __ldg(&Wl2[(size_t)i * 256 + tid]);
#pragma unroll
            for (int g = 0; g < 16; g++) acc[g] = fmaf(h_s[g][i], w, acc[g]);
        }
        __syncthreads();
#pragma unroll
        for (int g = 0; g < 16; g++) h_s[g][tid] = fmaxf(acc[g], 0.f);
    }
    __syncthreads();
    {
        int g = tid >> 4;
        int lane = tid & 15;
        float s = 0.f;
        for (int j = lane; j < 256; j += 16) s += h_s[g][j] * __ldg(&Wl3[j]);
#pragma unroll
        for (int off = 8; off > 0; off >>= 1)
            s += __shfl_down_sync(0xFFFFFFFFu, s, off, 16);
        if (lane == 0) out[gBase + g] = s + bl3[0];
    }
}

// ---------------- launch -----------------------------------------------------
extern "C" void kernel_launch(void* const* d_in, const int* in_sizes, int n_in,
                              void* d_out, int out_size) {
    const float* feats_node  = (const float*)d_in[0];
    const float* feats_graph = (const float*)d_in[1];
    const float* W1 = (const float*)d_in[2];
    const float* b1 = (const float*)d_in[3];
    const float* W2 = (const float*)d_in[4];
    const float* b2 = (const float*)d_in[5];
    const float* W3 = (const float*)d_in[6];
    const float* b3 = (const float*)d_in[7];
    const float* Wl1 = (const float*)d_in[8];
    const float* bl1 = (const float*)d_in[9];
    const float* Wl2 = (const float*)d_in[10];
    const float* bl2 = (const float*)d_in[11];
    const float* Wl3 = (const float*)d_in[12];
    const float* bl3 = (const float*)d_in[13];
    const int* src = (const int*)d_in[14];
    const int* dst = (const int*)d_in[15];
    const int* gid = (const int*)d_in[16];
    float* out = (float*)d_out;

    void *p_agg, *p_f16, *p_x16, *p_y16;
    cudaGetSymbolAddress(&p_agg, g_agg);
    cudaGetSymbolAddress(&p_f16, g_f16);
    cudaGetSymbolAddress(&p_x16, g_x16);
    cudaGetSymbolAddress(&p_y16, g_y16);
    float* agg = (float*)p_agg;
    __nv_bfloat16* f16 = (__nv_bfloat16*)p_f16;
    __nv_bfloat16* x16 = (__nv_bfloat16*)p_x16;
    __nv_bfloat16* y16 = (__nv_bfloat16*)p_y16;

    const int SMEM64  = (64 * (IN_FEATS + 4) + 2 * 32 * 136) * 4;
    const int SMEM128 = (64 * (HIDDEN + 4)   + 2 * 32 * 136) * 4;
    cudaFuncSetAttribute(gemm_tc_kernel<IN_FEATS, true, true, false>,
                         cudaFuncAttributeMaxDynamicSharedMemorySize, SMEM64);
    cudaFuncSetAttribute(gemm_tc_kernel<HIDDEN, true, true, false>,
                         cudaFuncAttributeMaxDynamicSharedMemorySize, SMEM128);
    cudaFuncSetAttribute(gemm_tc_kernel<HIDDEN, false, false, true>,
                         cudaFuncAttributeMaxDynamicSharedMemorySize, SMEM128);

    // --- preprocessing: degrees, scan (+coeffs/gcnt/feats->bf16/gsum-zero), fill
    zero_misc_kernel<<<(N_NODES + 255) / 256, 256>>>();
    degree_kernel<<<(E_HALF + 255) / 256, 256>>>(src, dst);
    scan_kernel<<<SCAN_NB, SCAN_BS>>>(gid, feats_node);
    fill_kernel<<<(E_HALF + 255) / 256, 256>>>(src, dst);

    const int gemm_blocks = (N_NODES + 63) / 64;

    // ---- layer 1: bf16 pull of pre-scaled feats, GEMM 64->128, relu, *c_out
    pull_bf16_kernel<IN_FEATS><<<(N_NODES * (IN_FEATS / 8) + 255) / 256, 256>>>(f16);
    gemm_tc_kernel<IN_FEATS, true, true, false><<<gemm_blocks, 256, SMEM64>>>(agg, W1, b1, x16, gid);

    // ---- layer 2: bf16 pull, GEMM 128->128, relu, *c_out
    pull_bf16_kernel<HIDDEN><<<(N_NODES * (HIDDEN / 8) + 255) / 256, 256>>>(x16);
    gemm_tc_kernel<HIDDEN, true, true, false><<<gemm_blocks, 256, SMEM128>>>(agg, W2, b2, y16, gid);

    // ---- layer 3: bf16 pull, GEMM 128->128 (no relu), fused mean-pool RED
    pull_bf16_kernel<HIDDEN><<<(N_NODES * (HIDDEN / 8) + 255) / 256, 256>>>(y16);
    gemm_tc_kernel<HIDDEN, false, false, true><<<gemm_blocks, 256, SMEM128>>>(agg, W3, b3, nullptr, gid);

    // ---- MLP head ----
    mlp_kernel<<<N_GRAPHS / 16, 256>>>(feats_graph, Wl1, bl1, Wl2, bl2, Wl3, bl3, out);
}

// round 8
// speedup vs baseline: 1.7515x; 1.2504x over previous
#include <cuda_runtime.h>
#include <cuda_bf16.h>
#include <cstdint>

#define N_NODES 50000
#define N_EDGES 600000
#define N_GRAPHS 2000
#define IN_FEATS 64
#define HIDDEN 128
#define SCAN_BS 1024
#define SCAN_NB ((N_NODES + SCAN_BS - 1) / SCAN_BS)   // 49
#define E_Q ((N_EDGES + 3) / 4)

// ---------------- scratch (device globals; no allocation allowed) ----------
__device__ int   g_deg_out[N_NODES];
__device__ int   g_deg_in[N_NODES];
__device__ float g_cout[N_NODES];
__device__ float g_cin[N_NODES];
__device__ int   g_rowstart[N_NODES + 1];
__device__ int   g_fill[N_NODES];
__device__ int   g_scanagg[SCAN_NB];
__device__ int   g_scanflag[SCAN_NB];
__device__ int   g_csr_src[N_EDGES];
__device__ __nv_bfloat16 g_agg16[(size_t)N_NODES * HIDDEN];  // pull output (bf16)
__device__ __nv_bfloat16 g_f16[(size_t)N_NODES * IN_FEATS];  // feats * c_out
__device__ __nv_bfloat16 g_x16[(size_t)N_NODES * HIDDEN];    // layer1 out * c_out
__device__ __nv_bfloat16 g_y16[(size_t)N_NODES * HIDDEN];    // layer2 out * c_out
__device__ float g_gsum[(size_t)N_GRAPHS * HIDDEN];
__device__ int   g_gcnt[N_GRAPHS];

// ---------------- helpers ---------------------------------------------------
__device__ __forceinline__ void red_add_v2(float* p, float x, float y) {
    asm volatile("red.global.add.v2.f32 [%0], {%1, %2};"
                 :: "l"(p), "f"(x), "f"(y) : "memory");
}
__device__ __forceinline__ void mma_bf16(float& d0, float& d1, float& d2, float& d3,
                                         uint32_t a0, uint32_t a1, uint32_t a2, uint32_t a3,
                                         uint32_t b0, uint32_t b1) {
    asm volatile(
        "mma.sync.aligned.m16n8k16.row.col.f32.bf16.bf16.f32 "
        "{%0,%1,%2,%3}, {%4,%5,%6,%7}, {%8,%9}, {%0,%1,%2,%3};"
        : "+f"(d0), "+f"(d1), "+f"(d2), "+f"(d3)
        : "r"(a0), "r"(a1), "r"(a2), "r"(a3), "r"(b0), "r"(b1));
}
__device__ __forceinline__ float2 bf2f2(uint32_t u) {
    __nv_bfloat162 h = *reinterpret_cast<__nv_bfloat162*>(&u);
    return __bfloat1622float2(h);
}
__device__ __forceinline__ uint32_t f2bf2(float lo, float hi) {
    __nv_bfloat162 h = __floats2bfloat162_rn(lo, hi);
    return *reinterpret_cast<uint32_t*>(&h);
}

// ---------------- zero + degree -----------------------------------------------
__global__ void zero_misc_kernel() {
    int i = blockIdx.x * blockDim.x + threadIdx.x;
    if (i < N_NODES) { g_deg_out[i] = 0; g_deg_in[i] = 0; }
    if (i < N_GRAPHS) g_gcnt[i] = 0;
    if (i < SCAN_NB) g_scanflag[i] = 0;
}

__global__ void degree_kernel(const int* __restrict__ src, const int* __restrict__ dst) {
    int e = blockIdx.x * blockDim.x + threadIdx.x;
    if (e >= E_Q) return;
#pragma unroll
    for (int q = 0; q < 4; q++) {
        int idx = e + q * E_Q;
        if (idx < N_EDGES) {
            atomicAdd(&g_deg_out[src[idx]], 1);
            atomicAdd(&g_deg_in[dst[idx]], 1);
        }
    }
}

// ---------------- single-kernel scan (decoupled lookback) + finalize ---------
// Also converts feats_node -> bf16 pre-scaled by c_out.
__global__ __launch_bounds__(SCAN_BS)
void scan_kernel(const int* __restrict__ gid, const float* __restrict__ feats) {
    int b = blockIdx.x;
    int i = b * SCAN_BS + threadIdx.x;
    int lane = threadIdx.x & 31, wid = threadIdx.x >> 5;
    int v = (i < N_NODES) ? g_deg_in[i] : 0;
    int x = v;
#pragma unroll
    for (int o = 1; o < 32; o <<= 1) {
        int y = __shfl_up_sync(0xFFFFFFFFu, x, o);
        if (lane >= o) x += y;
    }
    __shared__ int wsum[32];
    __shared__ int s_prefix;
    if (lane == 31) wsum[wid] = x;
    __syncthreads();
    if (wid == 0) {
        int w = wsum[lane];
#pragma unroll
        for (int o = 1; o < 32; o <<= 1) {
            int y = __shfl_up_sync(0xFFFFFFFFu, w, o);
            if (lane >= o) w += y;
        }
        wsum[lane] = w;
    }
    __syncthreads();
    int excl = x - v + (wid > 0 ? wsum[wid - 1] : 0);

    if (threadIdx.x == 0) {
        g_scanagg[b] = wsum[31];
        __threadfence();
        atomicExch(&g_scanflag[b], 1);
    }
    if (wid == 0) {
        int pre = 0;
        for (int base = 0; base < b; base += 32) {
            int idx = base + lane;
            int val = 0;
            if (idx < b) {
                while (atomicAdd(&g_scanflag[idx], 0) == 0) {}
                val = g_scanagg[idx];
            }
#pragma unroll
            for (int o = 16; o > 0; o >>= 1)
                val += __shfl_xor_sync(0xFFFFFFFFu, val, o);
            pre += val;
        }
        if (lane == 0) s_prefix = pre;
    }
    __syncthreads();
    int prefix = s_prefix;

    if (i < N_NODES) {
        int r = excl + prefix;
        g_rowstart[i] = r;
        g_fill[i] = r;
        g_cout[i] = rsqrtf(fmaxf((float)g_deg_out[i], 1.0f));
        g_cin[i]  = rsqrtf(fmaxf((float)g_deg_in[i], 1.0f));
        atomicAdd(&g_gcnt[gid[i]], 1);
    }
    if (i == 0) g_rowstart[N_NODES] = N_EDGES;
    __syncthreads();   // g_cout for this block's node range now visible

    // convert this block's feats rows to bf16, pre-scaled by c_out (coalesced)
    constexpr int CPN = IN_FEATS / 4;   // float4 chunks per node (16)
    int nodeBase = b * SCAN_BS;
    for (int idx = threadIdx.x; idx < SCAN_BS * CPN; idx += SCAN_BS) {
        int node = nodeBase + idx / CPN;
        int l4 = idx % CPN;
        if (node < N_NODES) {
            float co = g_cout[node];
            float4 fv = __ldg(reinterpret_cast<const float4*>(
                feats + (size_t)node * IN_FEATS + l4 * 4));
            uint2 st;
            st.x = f2bf2(fv.x * co, fv.y * co);
            st.y = f2bf2(fv.z * co, fv.w * co);
            *reinterpret_cast<uint2*>(g_f16 + (size_t)node * IN_FEATS + l4 * 4) = st;
        }
    }

    for (int k = b * SCAN_BS + threadIdx.x; k < N_GRAPHS * HIDDEN; k += SCAN_NB * SCAN_BS)
        g_gsum[k] = 0.0f;
}

__global__ void fill_kernel(const int* __restrict__ src, const int* __restrict__ dst) {
    int e = blockIdx.x * blockDim.x + threadIdx.x;
    if (e >= E_Q) return;
#pragma unroll
    for (int q = 0; q < 4; q++) {
        int idx = e + q * E_Q;
        if (idx < N_EDGES) {
            int pos = atomicAdd(&g_fill[dst[idx]], 1);
            g_csr_src[pos] = src[idx];
        }
    }
}

// ---------------- bf16 pull aggregation (bf16 in, bf16 out) ------------------
// agg16[d] = c_in[d] * sum_{s in N(d)} x16[s]   (x16 already carries c_out)
template <int F>
__global__ __launch_bounds__(256)
void pull_bf16_kernel(const __nv_bfloat16* __restrict__ x16) {
    constexpr int LPN = F / 8;                 // lanes per node
    int t = blockIdx.x * blockDim.x + threadIdx.x;
    int node = t / LPN;
    int lane = t % LPN;
    if (node >= N_NODES) return;
    int j = g_rowstart[node];
    int end = g_rowstart[node + 1];
    float2 a0 = make_float2(0.f, 0.f), a1 = a0, a2 = a0, a3 = a0;
    for (; j + 1 < end; j += 2) {
        int s0 = __ldg(&g_csr_src[j]);
        int s1 = __ldg(&g_csr_src[j + 1]);
        uint4 u0 = __ldg(reinterpret_cast<const uint4*>(x16 + (size_t)s0 * F + lane * 8));
        uint4 u1 = __ldg(reinterpret_cast<const uint4*>(x16 + (size_t)s1 * F + lane * 8));
        float2 f;
        f = bf2f2(u0.x); a0.x += f.x; a0.y += f.y;
        f = bf2f2(u0.y); a1.x += f.x; a1.y += f.y;
        f = bf2f2(u0.z); a2.x += f.x; a2.y += f.y;
        f = bf2f2(u0.w); a3.x += f.x; a3.y += f.y;
        f = bf2f2(u1.x); a0.x += f.x; a0.y += f.y;
        f = bf2f2(u1.y); a1.x += f.x; a1.y += f.y;
        f = bf2f2(u1.z); a2.x += f.x; a2.y += f.y;
        f = bf2f2(u1.w); a3.x += f.x; a3.y += f.y;
    }
    if (j < end) {
        int s0 = __ldg(&g_csr_src[j]);
        uint4 u0 = __ldg(reinterpret_cast<const uint4*>(x16 + (size_t)s0 * F + lane * 8));
        float2 f;
        f = bf2f2(u0.x); a0.x += f.x; a0.y += f.y;
        f = bf2f2(u0.y); a1.x += f.x; a1.y += f.y;
        f = bf2f2(u0.z); a2.x += f.x; a2.y += f.y;
        f = bf2f2(u0.w); a3.x += f.x; a3.y += f.y;
    }
    float ci = __ldg(&g_cin[node]);
    uint4 o;
    o.x = f2bf2(a0.x * ci, a0.y * ci);
    o.y = f2bf2(a1.x * ci, a1.y * ci);
    o.z = f2bf2(a2.x * ci, a2.y * ci);
    o.w = f2bf2(a3.x * ci, a3.y * ci);
    *reinterpret_cast<uint4*>(g_agg16 + (size_t)node * F + lane * 8) = o;
}

// ---------------- tensor-core GEMM (bf16 m16n8k16 mma.sync): -----------------
// C[N,128] = A16[N,FIN] @ W[FIN,128] + b. BM=64, BN=128, 256 threads (8 warps).
// Warp w: M-tile = (w%4)*16, N-range = (w/4)*64 (8 n8-tiles).
// Smem: A bf16 [64][FIN+8]; W k-pair-packed u32 [2][16][136].
template <int FIN, bool RELU, bool SCALE_OUT, bool POOL>
__global__ __launch_bounds__(256)
void gemm_tc_kernel(const __nv_bfloat16* __restrict__ A16,
                    const float* __restrict__ W,
                    const float* __restrict__ bias,
                    __nv_bfloat16* __restrict__ C16,
                    const int* __restrict__ gid) {
    extern __shared__ uint32_t smem[];
    constexpr int KPAD = FIN + 8;          // u16 units per A row
    constexpr int NPAD = 136;              // u32 units per W kpair row
    constexpr int NCH = FIN / 32;          // 32-k chunks
    uint16_t* At = reinterpret_cast<uint16_t*>(smem);        // 64 * KPAD u16
    uint32_t* Ws = smem + (64 * KPAD) / 2;                    // 2 * 16 * NPAD u32

    int tid = threadIdx.x;
    int warp = tid >> 5;
    int lane = tid & 31;
    int rowBase = blockIdx.x * 64;

    // ---- stage A tile (64 x FIN bf16): straight uint4 copies ----
    constexpr int C8 = FIN / 8;            // uint4 chunks per row
    for (int t = tid; t < 64 * C8; t += 256) {
        int row = t / C8;
        int k8 = t % C8;
        int gr = rowBase + row;
        uint4 u = make_uint4(0u, 0u, 0u, 0u);
        if (gr < N_NODES)
            u = __ldg(reinterpret_cast<const uint4*>(A16 + (size_t)gr * FIN + k8 * 8));
        *reinterpret_cast<uint4*>(At + row * KPAD + k8 * 8) = u;
    }
    // ---- stage W chunk 0: k-pair packed u32 {W[2kp][n], W[2kp+1][n]} ----
    {
#pragma unroll
        for (int t = 0; t < 4; t++) {
            int p = tid + t * 256;         // 0..1023 : kp = p>>6 (0..15), n2 = p&63
            int kp = p >> 6;
            int n = (p & 63) * 2;
            float2 lo = __ldg(reinterpret_cast<const float2*>(W + (size_t)(2 * kp) * 128 + n));
            float2 hi = __ldg(reinterpret_cast<const float2*>(W + (size_t)(2 * kp + 1) * 128 + n));
            uint2 st;
            st.x = f2bf2(lo.x, hi.x);
            st.y = f2bf2(lo.y, hi.y);
            *reinterpret_cast<uint2*>(Ws + kp * NPAD + n) = st;
        }
    }
    __syncthreads();

    int m0 = (warp & 3) * 16;
    int n0 = (warp >> 2) * 64;
    int lq = lane & 3;
    int lg = lane >> 2;

    float acc[8][4];
#pragma unroll
    for (int nt = 0; nt < 8; nt++)
#pragma unroll
        for (int j = 0; j < 4; j++) acc[nt][j] = 0.f;

    const uint16_t* arow0 = At + (m0 + lg) * KPAD + 2 * lq;
    const uint16_t* arow1 = arow0 + 8 * KPAD;

#pragma unroll
    for (int ch = 0; ch < NCH; ch++) {
        int cur = ch & 1;
        // prefetch next W chunk
        if (ch + 1 < NCH) {
#pragma unroll
            for (int t = 0; t < 4; t++) {
                int p = tid + t * 256;
                int kp = p >> 6;
                int n = (p & 63) * 2;
                int kg = (ch + 1) * 32 + 2 * kp;
                float2 lo = __ldg(reinterpret_cast<const float2*>(W + (size_t)kg * 128 + n));
                float2 hi = __ldg(reinterpret_cast<const float2*>(W + (size_t)(kg + 1) * 128 + n));
                uint2 st;
                st.x = f2bf2(lo.x, hi.x);
                st.y = f2bf2(lo.y, hi.y);
                *reinterpret_cast<uint2*>(Ws + (cur ^ 1) * 16 * NPAD + kp * NPAD + n) = st;
            }
        }
        const uint32_t* wsb = Ws + cur * 16 * NPAD;
#pragma unroll
        for (int ks = 0; ks < 2; ks++) {
            int kb = ch * 32 + ks * 16;
            uint32_t a0 = *reinterpret_cast<const uint32_t*>(arow0 + kb);
            uint32_t a1 = *reinterpret_cast<const uint32_t*>(arow1 + kb);
            uint32_t a2 = *reinterpret_cast<const uint32_t*>(arow0 + kb + 8);
            uint32_t a3 = *reinterpret_cast<const uint32_t*>(arow1 + kb + 8);
            const uint32_t* b0row = wsb + (ks * 8 + lq) * NPAD + n0 + lg;
            const uint32_t* b1row = b0row + 4 * NPAD;
#pragma unroll
            for (int nt = 0; nt < 8; nt++) {
                uint32_t b0 = b0row[nt * 8];
                uint32_t b1 = b1row[nt * 8];
                mma_bf16(acc[nt][0], acc[nt][1], acc[nt][2], acc[nt][3],
                         a0, a1, a2, a3, b0, b1);
            }
        }
        if (ch + 1 < NCH) __syncthreads();
    }

    // ---- epilogue ----
    int r_lo = rowBase + m0 + lg;
    int r_hi = r_lo + 8;
    float co_lo = 1.f, co_hi = 1.f;
    if (SCALE_OUT) {
        if (r_lo < N_NODES) co_lo = __ldg(&g_cout[r_lo]);
        if (r_hi < N_NODES) co_hi = __ldg(&g_cout[r_hi]);
    }
    int g_lo = 0, g_hi = 0;
    if (POOL) {
        if (r_lo < N_NODES) g_lo = __ldg(&gid[r_lo]);
        if (r_hi < N_NODES) g_hi = __ldg(&gid[r_hi]);
    }
#pragma unroll
    for (int nt = 0; nt < 8; nt++) {
        int col = n0 + nt * 8 + 2 * lq;
        float2 bb = __ldg(reinterpret_cast<const float2*>(bias + col));
        float v0 = acc[nt][0] + bb.x, v1 = acc[nt][1] + bb.y;
        float v2 = acc[nt][2] + bb.x, v3 = acc[nt][3] + bb.y;
        if (RELU) {
            v0 = fmaxf(v0, 0.f); v1 = fmaxf(v1, 0.f);
            v2 = fmaxf(v2, 0.f); v3 = fmaxf(v3, 0.f);
        }
        if (SCALE_OUT) { v0 *= co_lo; v1 *= co_lo; v2 *= co_hi; v3 *= co_hi; }
        if (r_lo < N_NODES) {
            if (POOL) {
                red_add_v2(g_gsum + (size_t)g_lo * 128 + col, v0, v1);
            } else {
                uint32_t h = f2bf2(v0, v1);
                *reinterpret_cast<uint32_t*>(C16 + (size_t)r_lo * 128 + col) = h;
            }
        }
        if (r_hi < N_NODES) {
            if (POOL) {
                red_add_v2(g_gsum + (size_t)g_hi * 128 + col, v2, v3);
            } else {
                uint32_t h = f2bf2(v2, v3);
                *reinterpret_cast<uint32_t*>(C16 + (size_t)r_hi * 128 + col) = h;
            }
        }
    }
}

// ---------------- fused MLP head (16 graphs per block) -----------------------
__global__ __launch_bounds__(256)
void mlp_kernel(const float* __restrict__ fg,
                const float* __restrict__ Wl1, const float* __restrict__ bl1,
                const float* __restrict__ Wl2, const float* __restrict__ bl2,
                const float* __restrict__ Wl3, const float* __restrict__ bl3,
                float* __restrict__ out) {
    __shared__ float in_s[16][132];
    __shared__ float h_s[16][256];

    int tid = threadIdx.x;
    int gBase = blockIdx.x * 16;

    for (int idx = tid; idx < 16 * 128; idx += 256) {
        int gl = idx >> 7, f = idx & 127;
        int g = gBase + gl;
        float c = (float)g_gcnt[g];
        in_s[gl][f] = g_gsum[(size_t)g * 128 + f] / fmaxf(c, 1.0f);
    }
    for (int idx = tid; idx < 16 * 3; idx += 256) {
        int gl = idx / 3, f = idx % 3;
        in_s[gl][128 + f] = fg[(size_t)(gBase + gl) * 3 + f];
    }
    __syncthreads();

    float acc[16];
    {
        float b = bl1[tid];
#pragma unroll
        for (int g = 0; g < 16; g++) acc[g] = b;
        for (int i = 0; i < 131; i++) {
            float w = __ldg(&Wl1[(size_t)i * 256 + tid]);
#pragma unroll
            for (int g = 0; g < 16; g++) acc[g] = fmaf(in_s[g][i], w, acc[g]);
        }
#pragma unroll
        for (int g = 0; g < 16; g++) h_s[g][tid] = fmaxf(acc[g], 0.f);
    }
    __syncthreads();
    {
        float b = bl2[tid];
#pragma unroll
        for (int g = 0; g < 16; g++) acc[g] = b;
        for (int i = 0; i < 256; i++) {
            float w = __ldg(&Wl2[(size_t)i * 256 + tid]);
#pragma unroll
            for (int g = 0; g < 16; g++) acc[g] = fmaf(h_s[g][i], w, acc[g]);
        }
        __syncthreads();
#pragma unroll
        for (int g = 0; g < 16; g++) h_s[g][tid] = fmaxf(acc[g], 0.f);
    }
    __syncthreads();
    {
        int g = tid >> 4;
        int lane = tid & 15;
        float s = 0.f;
        for (int j = lane; j < 256; j += 16) s += h_s[g][j] * __ldg(&Wl3[j]);
#pragma unroll
        for (int off = 8; off > 0; off >>= 1)
            s += __shfl_down_sync(0xFFFFFFFFu, s, off, 16);
        if (lane == 0) out[gBase + g] = s + bl3[0];
    }
}

// ---------------- launch -----------------------------------------------------
extern "C" void kernel_launch(void* const* d_in, const int* in_sizes, int n_in,
                              void* d_out, int out_size) {
    const float* feats_node  = (const float*)d_in[0];
    const float* feats_graph = (const float*)d_in[1];
    const float* W1 = (const float*)d_in[2];
    const float* b1 = (const float*)d_in[3];
    const float* W2 = (const float*)d_in[4];
    const float* b2 = (const float*)d_in[5];
    const float* W3 = (const float*)d_in[6];
    const float* b3 = (const float*)d_in[7];
    const float* Wl1 = (const float*)d_in[8];
    const float* bl1 = (const float*)d_in[9];
    const float* Wl2 = (const float*)d_in[10];
    const float* bl2 = (const float*)d_in[11];
    const float* Wl3 = (const float*)d_in[12];
    const float* bl3 = (const float*)d_in[13];
    const int* src = (const int*)d_in[14];
    const int* dst = (const int*)d_in[15];
    const int* gid = (const int*)d_in[16];
    float* out = (float*)d_out;

    void *p_agg16, *p_f16, *p_x16, *p_y16;
    cudaGetSymbolAddress(&p_agg16, g_agg16);
    cudaGetSymbolAddress(&p_f16, g_f16);
    cudaGetSymbolAddress(&p_x16, g_x16);
    cudaGetSymbolAddress(&p_y16, g_y16);
    __nv_bfloat16* agg16 = (__nv_bfloat16*)p_agg16;
    __nv_bfloat16* f16 = (__nv_bfloat16*)p_f16;
    __nv_bfloat16* x16 = (__nv_bfloat16*)p_x16;
    __nv_bfloat16* y16 = (__nv_bfloat16*)p_y16;

    // dynamic smem: A bf16 tile + 2 packed W buffers (all < 48KB, no attribute needed)
    const int SMEM64  = 64 * (IN_FEATS + 8) * 2 + 2 * 16 * 136 * 4;   // 26624
    const int SMEM128 = 64 * (HIDDEN + 8) * 2   + 2 * 16 * 136 * 4;   // 34816

    // --- preprocessing: degrees, scan (+coeffs/gcnt/feats->bf16/gsum-zero), fill
    zero_misc_kernel<<<(N_NODES + 255) / 256, 256>>>();
    degree_kernel<<<(E_Q + 255) / 256, 256>>>(src, dst);
    scan_kernel<<<SCAN_NB, SCAN_BS>>>(gid, feats_node);
    fill_kernel<<<(E_Q + 255) / 256, 256>>>(src, dst);

    const int gemm_blocks = (N_NODES + 63) / 64;

    // ---- layer 1: bf16 pull of pre-scaled feats, GEMM 64->128, relu, *c_out
    pull_bf16_kernel<IN_FEATS><<<(N_NODES * (IN_FEATS / 8) + 255) / 256, 256>>>(f16);
    gemm_tc_kernel<IN_FEATS, true, true, false><<<gemm_blocks, 256, SMEM64>>>(agg16, W1, b1, x16, gid);

    // ---- layer 2: bf16 pull, GEMM 128->128, relu, *c_out
    pull_bf16_kernel<HIDDEN><<<(N_NODES * (HIDDEN / 8) + 255) / 256, 256>>>(x16);
    gemm_tc_kernel<HIDDEN, true, true, false><<<gemm_blocks, 256, SMEM128>>>(agg16, W2, b2, y16, gid);

    // ---- layer 3: bf16 pull, GEMM 128->128 (no relu), fused mean-pool RED
    pull_bf16_kernel<HIDDEN><<<(N_NODES * (HIDDEN / 8) + 255) / 256, 256>>>(y16);
    gemm_tc_kernel<HIDDEN, false, false, true><<<gemm_blocks, 256, SMEM128>>>(agg16, W3, b3, nullptr, gid);

    // ---- MLP head ----
    mlp_kernel<<<N_GRAPHS / 16, 256>>>(feats_graph, Wl1, bl1, Wl2, bl2, Wl3, bl3, out);
}